// round 14
// baseline (speedup 1.0000x reference)
#include <cuda_runtime.h>
#include <cuda_bf16.h>
#include <cstdint>

#define BATCH 4
#define SEQ 2048
#define DM 1024
#define DH 128
#define ROWS (BATCH * SEQ)   // 8192

// ---------------------------------------------------------------------------
// Scratch (__device__ globals per allocation rules)
// ---------------------------------------------------------------------------
__device__ __align__(16) __nv_bfloat16 g_qhi[ROWS * DH];
__device__ __align__(16) __nv_bfloat16 g_qlo[ROWS * DH];
__device__ __align__(16) __nv_bfloat16 g_khi[ROWS * DH];
__device__ __align__(16) __nv_bfloat16 g_klo[ROWS * DH];
__device__ __align__(16) __nv_bfloat16 g_vthi[BATCH * DH * SEQ];  // [b][d][key]
__device__ __align__(16) __nv_bfloat16 g_vtlo[BATCH * DH * SEQ];
__device__ __align__(16) __nv_bfloat16 g_ctxhi[ROWS * DH];
__device__ __align__(16) __nv_bfloat16 g_ctxlo[ROWS * DH];
// split-K attention partials: slot = (b*16 + qt-16)*2 + part
__device__ __align__(16) float g_pO[128][64][DH];
__device__ float g_pm[128][64];
__device__ float g_pl[128][64];
// transposed bf16 hi/lo weights: wT[z][n][k] = w_z[k][n]
__device__ __align__(16) __nv_bfloat16 g_wThi[3 * DH * DM];
__device__ __align__(16) __nv_bfloat16 g_wTlo[3 * DH * DM];
__device__ __align__(16) __nv_bfloat16 g_woThi[DM * DH];
__device__ __align__(16) __nv_bfloat16 g_woTlo[DM * DH];

// ---------------------------------------------------------------------------
// helpers
// ---------------------------------------------------------------------------
__device__ __forceinline__ uint32_t smem_u32(const void* p) {
    uint32_t a;
    asm("{ .reg .u64 t; cvta.to.shared.u64 t, %1; cvt.u32.u64 %0, t; }"
        : "=r"(a) : "l"(p));
    return a;
}
__device__ __forceinline__ uint32_t pack_bf16x2(float x, float y) {
    __nv_bfloat162 t(__float2bfloat16(x), __float2bfloat16(y));  // x -> low
    return *(uint32_t*)&t;
}
__device__ __forceinline__ void split_bf16(float v, __nv_bfloat16& h, float& lo) {
    h = __float2bfloat16(v);
    lo = v - __bfloat162float(h);
}
__device__ __forceinline__ void split2(float x, float y, uint32_t& hi, uint32_t& lo) {
    __nv_bfloat16 hx, hy; float lx, ly;
    split_bf16(x, hx, lx); split_bf16(y, hy, ly);
    __nv_bfloat162 H(hx, hy);
    hi = *(uint32_t*)&H;
    lo = pack_bf16x2(lx, ly);
}

// mma.sync m16n8k16 bf16 -> f32 (HMMA pipe, target-portable)
#define MMA4(c, a, b) asm volatile( \
    "mma.sync.aligned.m16n8k16.row.col.f32.bf16.bf16.f32 " \
    "{%0,%1,%2,%3}, {%4,%5,%6,%7}, {%8,%9}, {%0,%1,%2,%3};" \
    : "+f"((c)[0]), "+f"((c)[1]), "+f"((c)[2]), "+f"((c)[3]) \
    : "r"((a)[0]), "r"((a)[1]), "r"((a)[2]), "r"((a)[3]), \
      "r"((b)[0]), "r"((b)[1]))

#define LDMX4(d, a) asm volatile( \
    "ldmatrix.sync.aligned.m8n8.x4.shared.b16 {%0,%1,%2,%3}, [%4];" \
    : "=r"((d)[0]), "=r"((d)[1]), "=r"((d)[2]), "=r"((d)[3]) : "r"(a))

#define CP_ASYNC16(dst, src) \
    asm volatile("cp.async.cg.shared.global [%0], [%1], 16;" \
                 :: "r"(dst), "l"(src) : "memory")
#define CP_COMMIT asm volatile("cp.async.commit_group;" ::: "memory")
#define CP_WAIT(n) asm volatile("cp.async.wait_group %0;" :: "n"(n) : "memory")

// ---------------------------------------------------------------------------
// Prep kernels
// ---------------------------------------------------------------------------
__global__ void prep_w_qkv(const float* __restrict__ wq,
                           const float* __restrict__ wk,
                           const float* __restrict__ wv) {
    int k = blockIdx.x, z = blockIdx.y, n = threadIdx.x;   // 128 thr
    const float* w = (z == 0) ? wq : (z == 1) ? wk : wv;
    float v = w[k * DH + n];
    __nv_bfloat16 h; float lo; split_bf16(v, h, lo);
    size_t o = (size_t)z * DH * DM + (size_t)n * DM + k;
    g_wThi[o] = h; g_wTlo[o] = __float2bfloat16(lo);
}
__global__ void prep_wo(const float* __restrict__ wo) {
    int k = blockIdx.x;                                    // 128 blocks, 256 thr
#pragma unroll
    for (int i = 0; i < 4; i++) {
        int n = threadIdx.x + i * 256;
        float v = wo[(size_t)k * DM + n];
        __nv_bfloat16 h; float lo; split_bf16(v, h, lo);
        g_woThi[(size_t)n * DH + k] = h;
        g_woTlo[(size_t)n * DH + k] = __float2bfloat16(lo);
    }
}

// ---------------------------------------------------------------------------
// QKV GEMM: BM=128, BN=128, BK=32, K=1024 (nc=32). grid (64, 3), 256 thr.
// 8 warps as 4m x 2n; warp tile 32x64. 3-stage cp.async + in-kernel X split.
// z==2 (V): epilogue transposes+splits into g_vt{hi,lo}[b][d][key] (CTA tile
// covers exactly 128 keys x all 128 d).
// smem: stage s @ s*40960: Ahi[128x80B], Alo +10240, Bhi +20480, Blo +30720;
//       f32 X scratch @ 122880: 2 slots x 16384.   Total 155648 B.
// ---------------------------------------------------------------------------
#define QABY 10240
#define QBBY 10240
#define QSTG (2 * QABY + 2 * QBBY)            // 40960
#define QKV_SMEM (3 * QSTG + 2 * 16384)       // 155648

__global__ __launch_bounds__(256, 1) void qkv_mma_kernel(const float* __restrict__ x) {
    extern __shared__ char smg[];
    const uint32_t sbase = smem_u32(smg);
    const int z = blockIdx.y, bx = blockIdx.x;
    const __nv_bfloat16* __restrict__ Bhig = g_wThi + (size_t)z * DH * DM;
    const __nv_bfloat16* __restrict__ Blog = g_wTlo + (size_t)z * DH * DM;
    const float* __restrict__ Af = x + (size_t)bx * 128 * DM;
    const int tid  = threadIdx.x;
    const int lane = tid & 31;
    const int wid  = tid >> 5;
    const int warpM = wid >> 1;           // 0..3
    const int warpN = wid & 1;            // 0..1
    const int qr = lane >> 2, qc = lane & 3;

    float acc[2][8][4];
#pragma unroll
    for (int mt = 0; mt < 2; mt++)
#pragma unroll
        for (int nt = 0; nt < 8; nt++)
#pragma unroll
            for (int i = 0; i < 4; i++) acc[mt][nt][i] = 0.f;

    auto issue = [&](int c) {
        const uint32_t bstg = sbase + (c % 3) * QSTG + 2 * QABY;
#pragma unroll
        for (int i = 0; i < 4; i++) {           // B: 1024 x 16B
            int u = tid + i * 256;
            int r = u >> 3, cc = u & 3, hf = (u >> 2) & 1;
            CP_ASYNC16(bstg + (hf ? QBBY : 0) + r * 80 + cc * 16,
                       (const char*)((hf ? Blog : Bhig) +
                                     (size_t)r * DM + c * 32 + cc * 8));
        }
        const uint32_t fstg = sbase + 3 * QSTG + (c & 1) * 16384;
#pragma unroll
        for (int i = 0; i < 4; i++) {           // X f32: 1024 x 16B
            int u = tid + i * 256;
            int r = u >> 3, j = u & 7;
            CP_ASYNC16(fstg + r * 128 + j * 16,
                       (const char*)(Af + (size_t)r * DM + c * 32 + j * 4));
        }
    };

    issue(0); CP_COMMIT;
    issue(1); CP_COMMIT;

    const uint32_t aoff = (warpM * 32 + (lane & 15)) * 80 + ((lane >> 4) & 1) * 16;
    const uint32_t boff = 2 * QABY + ((lane & 16) ? QBBY : 0) +
                          (warpN * 64 + (lane & 7)) * 80 + ((lane >> 3) & 1) * 16;

    for (int c = 0; c < 32; c++) {
        if (c + 1 < 32) CP_WAIT(1); else CP_WAIT(0);
        __syncthreads();

        const uint32_t bufb = sbase + (c % 3) * QSTG;
        const uint32_t fstg = sbase + 3 * QSTG + (c & 1) * 16384;
        // split f32 X slot -> bf16 hi/lo A stage
#pragma unroll
        for (int i = 0; i < 4; i++) {
            int u = tid + i * 256;
            int r = u >> 3, j = u & 7;
            float vx, vy, vz, vw;
            asm volatile("ld.shared.v4.f32 {%0,%1,%2,%3}, [%4];"
                         : "=f"(vx), "=f"(vy), "=f"(vz), "=f"(vw)
                         : "r"(fstg + r * 128 + j * 16));
            uint32_t h0, l0, h1, l1;
            split2(vx, vy, h0, l0);
            split2(vz, vw, h1, l1);
            asm volatile("st.shared.v2.b32 [%0], {%1,%2};"
                         :: "r"(bufb + r * 80 + j * 8), "r"(h0), "r"(h1) : "memory");
            asm volatile("st.shared.v2.b32 [%0], {%1,%2};"
                         :: "r"(bufb + QABY + r * 80 + j * 8), "r"(l0), "r"(l1) : "memory");
        }
        __syncthreads();
        if (c + 2 < 32) { issue(c + 2); CP_COMMIT; }

#pragma unroll
        for (int s = 0; s < 2; s++) {
            uint32_t ah[2][4], al[2][4];
#pragma unroll
            for (int mt = 0; mt < 2; mt++) {
                LDMX4(ah[mt], bufb + aoff + mt * 16 * 80 + s * 32);
                LDMX4(al[mt], bufb + QABY + aoff + mt * 16 * 80 + s * 32);
            }
#pragma unroll
            for (int nt = 0; nt < 8; nt++) {
                uint32_t bb[4];
                LDMX4(bb, bufb + boff + nt * 8 * 80 + s * 32);
                uint32_t bh[2] = {bb[0], bb[1]}, bl[2] = {bb[2], bb[3]};
#pragma unroll
                for (int mt = 0; mt < 2; mt++) {
                    MMA4(acc[mt][nt], ah[mt], bh);
                    MMA4(acc[mt][nt], ah[mt], bl);
                    MMA4(acc[mt][nt], al[mt], bh);
                }
            }
        }
    }

    if (z < 2) {
        __nv_bfloat16* Chi = ((z == 0) ? g_qhi : g_khi) + (size_t)bx * 128 * DH;
        __nv_bfloat16* Clo = ((z == 0) ? g_qlo : g_klo) + (size_t)bx * 128 * DH;
#pragma unroll
        for (int mt = 0; mt < 2; mt++)
#pragma unroll
            for (int nt = 0; nt < 8; nt++) {
                int r = warpM * 32 + mt * 16 + qr;
                int col = warpN * 64 + nt * 8 + qc * 2;
                uint32_t h0, l0, h1, l1;
                split2(acc[mt][nt][0], acc[mt][nt][1], h0, l0);
                split2(acc[mt][nt][2], acc[mt][nt][3], h1, l1);
                ((uint32_t*)(Chi + (size_t)r * DH))[col >> 1] = h0;
                ((uint32_t*)(Clo + (size_t)r * DH))[col >> 1] = l0;
                ((uint32_t*)(Chi + (size_t)(r + 8) * DH))[col >> 1] = h1;
                ((uint32_t*)(Clo + (size_t)(r + 8) * DH))[col >> 1] = l1;
            }
    } else {
        // V: stage f32 tile [key(row)][d(col)], transpose+split -> g_vt
        float* ts = (float*)smg;          // 128 x 132 f32 = 67584 B
        __syncthreads();                  // done with stage buffers
#pragma unroll
        for (int mt = 0; mt < 2; mt++)
#pragma unroll
            for (int nt = 0; nt < 8; nt++) {
                int r = warpM * 32 + mt * 16 + qr;
                int col = warpN * 64 + nt * 8 + qc * 2;
                ts[r * 132 + col]       = acc[mt][nt][0];
                ts[r * 132 + col + 1]   = acc[mt][nt][1];
                ts[(r + 8) * 132 + col]     = acc[mt][nt][2];
                ts[(r + 8) * 132 + col + 1] = acc[mt][nt][3];
            }
        __syncthreads();
        const int rb = bx * 128;
        const int b  = rb >> 11;          // / SEQ
        const int kb = rb & (SEQ - 1);
        const int d  = tid >> 1, hf2 = tid & 1;
        uint32_t* ohi = (uint32_t*)(g_vthi + ((size_t)b * DH + d) * SEQ + kb + hf2 * 64);
        uint32_t* olo = (uint32_t*)(g_vtlo + ((size_t)b * DH + d) * SEQ + kb + hf2 * 64);
#pragma unroll
        for (int j = 0; j < 32; j++) {
            int key = hf2 * 64 + j * 2;
            uint32_t hv, lv;
            split2(ts[key * 132 + d], ts[(key + 1) * 132 + d], hv, lv);
            ohi[j] = hv; olo[j] = lv;
        }
    }
}

// ---------------------------------------------------------------------------
// Output projection GEMM (unchanged from R12): BM=64, n-slab 128, nc=4.
// ---------------------------------------------------------------------------
#define ABY  5120
#define BBY  10240
#define STGB (2 * ABY + 2 * BBY)              // 30720
#define OUT_SMEM (3 * STGB)                   // 92160

__global__ __launch_bounds__(256, 2) void out_mma_kernel(float* __restrict__ out) {
    extern __shared__ char smg[];
    const uint32_t sbase = smem_u32(smg);
    const int bx = blockIdx.x, by = blockIdx.y;
    const __nv_bfloat16* __restrict__ Ahi = g_ctxhi + (size_t)bx * 64 * DH;
    const __nv_bfloat16* __restrict__ Alo = g_ctxlo + (size_t)bx * 64 * DH;
    const __nv_bfloat16* __restrict__ Bhig = g_woThi + (size_t)by * 128 * DH;
    const __nv_bfloat16* __restrict__ Blog = g_woTlo + (size_t)by * 128 * DH;
    float* __restrict__ C = out + (size_t)bx * 64 * DM + by * 128;
    const int nc = 4;
    const int tid  = threadIdx.x;
    const int lane = tid & 31;
    const int wid  = tid >> 5;
    const int warpM = wid >> 2;
    const int warpN = wid & 3;
    const int qr = lane >> 2, qc = lane & 3;

    float acc[2][4][4];
#pragma unroll
    for (int mt = 0; mt < 2; mt++)
#pragma unroll
        for (int nt = 0; nt < 4; nt++)
#pragma unroll
            for (int i = 0; i < 4; i++) acc[mt][nt][i] = 0.f;

    auto issue = [&](int c) {
        const uint32_t bstg = sbase + (c % 3) * STGB + 2 * ABY;
#pragma unroll
        for (int i = 0; i < 4; i++) {
            int u = tid + i * 256;
            int r = u >> 3, cc = u & 3, hf = (u >> 2) & 1;
            CP_ASYNC16(bstg + (hf ? BBY : 0) + r * 80 + cc * 16,
                       (const char*)((hf ? Blog : Bhig) +
                                     (size_t)r * DH + c * 32 + cc * 8));
        }
        const uint32_t astg = sbase + (c % 3) * STGB;
#pragma unroll
        for (int i = 0; i < 2; i++) {
            int u = tid + i * 256;
            int r = u >> 3, cc = u & 3, hf = (u >> 2) & 1;
            CP_ASYNC16(astg + (hf ? ABY : 0) + r * 80 + cc * 16,
                       (const char*)((hf ? Alo : Ahi) +
                                     (size_t)r * DH + c * 32 + cc * 8));
        }
    };

    issue(0); CP_COMMIT;
    issue(1); CP_COMMIT;

    const uint32_t aoff_hi = (warpM * 32 + (lane & 15)) * 80 + ((lane >> 4) & 1) * 16;
    const uint32_t aoff_lo = aoff_hi + ABY;
    const uint32_t boff = 2 * ABY + ((lane & 16) ? BBY : 0) +
                          (warpN * 32 + (lane & 7)) * 80 + ((lane >> 3) & 1) * 16;

    for (int c = 0; c < nc; c++) {
        if (c + 1 < nc) CP_WAIT(1); else CP_WAIT(0);
        __syncthreads();
        const uint32_t bufb = sbase + (c % 3) * STGB;
        if (c + 2 < nc) { issue(c + 2); CP_COMMIT; }

#pragma unroll
        for (int s = 0; s < 2; s++) {
            uint32_t ah[2][4], al[2][4];
#pragma unroll
            for (int mt = 0; mt < 2; mt++) {
                LDMX4(ah[mt], bufb + aoff_hi + mt * 16 * 80 + s * 32);
                LDMX4(al[mt], bufb + aoff_lo + mt * 16 * 80 + s * 32);
            }
#pragma unroll
            for (int nt = 0; nt < 4; nt++) {
                uint32_t bb[4];
                LDMX4(bb, bufb + boff + nt * 8 * 80 + s * 32);
                uint32_t bh[2] = {bb[0], bb[1]}, bl[2] = {bb[2], bb[3]};
#pragma unroll
                for (int mt = 0; mt < 2; mt++) {
                    MMA4(acc[mt][nt], ah[mt], bh);
                    MMA4(acc[mt][nt], ah[mt], bl);
                    MMA4(acc[mt][nt], al[mt], bh);
                }
            }
        }
        __syncthreads();
    }

#pragma unroll
    for (int mt = 0; mt < 2; mt++)
#pragma unroll
        for (int nt = 0; nt < 4; nt++) {
            int r = warpM * 32 + mt * 16 + qr;
            int col = warpN * 32 + nt * 8 + qc * 2;
            *(float2*)(C + (size_t)r * DM + col) =
                make_float2(acc[mt][nt][0], acc[mt][nt][1]);
            *(float2*)(C + (size_t)(r + 8) * DM + col) =
                make_float2(acc[mt][nt][2], acc[mt][nt][3]);
        }
}

// ---------------------------------------------------------------------------
// Tensor-core causal flash attention, split-K, DOUBLE-buffered (R12 verbatim).
// grid = 192; smem = 178176 B.
// ---------------------------------------------------------------------------
#define ATTN_SMEM 178176

__device__ __forceinline__ void attn_issue_tile(
    uint32_t sbase, int tid, int b, int kt, int p, size_t bbase)
{
    const uint32_t base = sbase + 34816 + p * 71680;
    const int k0 = kt * 64;
    const char* khi_g = (const char*)(g_khi + (bbase + k0) * DH);
    const char* klo_g = (const char*)(g_klo + (bbase + k0) * DH);
    const char* vhi_g = (const char*)g_vthi + (((size_t)b * DH) * SEQ + k0) * 2;
    const char* vlo_g = (const char*)g_vtlo + (((size_t)b * DH) * SEQ + k0) * 2;
#pragma unroll
    for (int i = 0; i < 8; i++) {
        int id = tid + i * 128;
        int r  = id >> 4, off  = (id & 15) * 16;   // K: 64 rows x 256B
        CP_ASYNC16(base + r * 272 + off, khi_g + (size_t)r * 256 + off);
        CP_ASYNC16(base + 17408 + r * 272 + off, klo_g + (size_t)r * 256 + off);
        int rv = id >> 3, offv = (id & 7) * 16;    // Vt: 128 rows x 128B
        CP_ASYNC16(base + 34816 + rv * 144 + offv,
                   vhi_g + (size_t)rv * (SEQ * 2) + offv);
        CP_ASYNC16(base + 53248 + rv * 144 + offv,
                   vlo_g + (size_t)rv * (SEQ * 2) + offv);
    }
}

__global__ __launch_bounds__(128, 1) void attn_mma_kernel()
{
    extern __shared__ char sm[];
    const uint32_t sbase = smem_u32(sm);
    const int tid  = threadIdx.x;
    const int lane = tid & 31;
    const int wq   = tid >> 5;
    const int qr   = lane >> 2, qc = lane & 3;

    const int bid = blockIdx.x;
    int b, qt, kt0, kt1, part;
    bool partial;
    if (bid < 64) {
        b = bid & 3; qt = 16 + (bid >> 2); kt0 = 0; kt1 = 15;
        partial = true; part = 0;
    } else if (bid < 128) {
        int i = bid - 64;
        b = i & 3; qt = 31 - (i >> 2); kt0 = 16; kt1 = qt;
        partial = true; part = 1;
    } else {
        int i = bid - 128;
        b = i & 3; qt = 15 - (i >> 2); kt0 = 0; kt1 = qt;
        partial = false; part = 0;
    }
    const int qb = qt * 64;
    const size_t bbase = (size_t)b * SEQ;
    const int ntiles = kt1 - kt0 + 1;
    const float scale = 0.08838834764831845f;

    {
        const char* qhi_g = (const char*)(g_qhi + (bbase + qb) * DH);
        const char* qlo_g = (const char*)(g_qlo + (bbase + qb) * DH);
#pragma unroll
        for (int i = 0; i < 8; i++) {
            int id = tid + i * 128;
            int r = id >> 4, off = (id & 15) * 16;
            CP_ASYNC16(sbase + r * 272 + off, qhi_g + (size_t)r * 256 + off);
            CP_ASYNC16(sbase + 17408 + r * 272 + off, qlo_g + (size_t)r * 256 + off);
        }
        attn_issue_tile(sbase, tid, b, kt0, 0, bbase);
        CP_COMMIT;
    }

    const uint32_t q_hi_addr = sbase + (wq * 16 + (lane & 15)) * 272 +
                               ((lane >> 4) & 1) * 16;
    const uint32_t q_lo_addr = q_hi_addr + 17408;
    const uint32_t k_off = ((lane & 16) ? 17408u : 0u) +
                           (lane & 7) * 272 + ((lane >> 3) & 1) * 16;
    const uint32_t v_off = 34816u + ((lane & 16) ? 18432u : 0u) +
                           (lane & 7) * 144 + ((lane >> 3) & 1) * 16;

    float O[16][4];
#pragma unroll
    for (int nf = 0; nf < 16; nf++)
#pragma unroll
        for (int i = 0; i < 4; i++) O[nf][i] = 0.f;
    float m0 = -1e30f, m1 = -1e30f, l0 = 0.f, l1 = 0.f;

    for (int t = 0; t < ntiles; t++) {
        const int kt = kt0 + t;
        const int p = t & 1;
        if (t + 1 < ntiles) {
            attn_issue_tile(sbase, tid, b, kt + 1, p ^ 1, bbase);
            CP_COMMIT;
            CP_WAIT(1);
        } else {
            CP_WAIT(0);
        }
        __syncthreads();

        const uint32_t base = sbase + 34816 + p * 71680;

        float sacc[8][4];
#pragma unroll
        for (int nf = 0; nf < 8; nf++)
#pragma unroll
            for (int i = 0; i < 4; i++) sacc[nf][i] = 0.f;

#pragma unroll
        for (int kf = 0; kf < 8; kf++) {
            uint32_t ah[4], al[4];
            LDMX4(ah, q_hi_addr + kf * 32);
            LDMX4(al, q_lo_addr + kf * 32);
#pragma unroll
            for (int nf = 0; nf < 8; nf++) {
                uint32_t bb[4];
                LDMX4(bb, base + k_off + nf * 2176 + kf * 32);
                uint32_t bh[2] = {bb[0], bb[1]}, bl[2] = {bb[2], bb[3]};
                MMA4(sacc[nf], ah, bh);
                MMA4(sacc[nf], ah, bl);
                MMA4(sacc[nf], al, bh);
            }
        }

#pragma unroll
        for (int nf = 0; nf < 8; nf++)
#pragma unroll
            for (int i = 0; i < 4; i++) sacc[nf][i] *= scale;
        if (kt == qt) {
            const int q0 = wq * 16 + qr, q1 = q0 + 8;
#pragma unroll
            for (int nf = 0; nf < 8; nf++) {
                const int key = nf * 8 + qc * 2;
                if (key > q0)     sacc[nf][0] = -1e30f;
                if (key + 1 > q0) sacc[nf][1] = -1e30f;
                if (key > q1)     sacc[nf][2] = -1e30f;
                if (key + 1 > q1) sacc[nf][3] = -1e30f;
            }
        }

        float mt0 = -1e30f, mt1 = -1e30f;
#pragma unroll
        for (int nf = 0; nf < 8; nf++) {
            mt0 = fmaxf(mt0, fmaxf(sacc[nf][0], sacc[nf][1]));
            mt1 = fmaxf(mt1, fmaxf(sacc[nf][2], sacc[nf][3]));
        }
        mt0 = fmaxf(mt0, __shfl_xor_sync(0xffffffffu, mt0, 1));
        mt0 = fmaxf(mt0, __shfl_xor_sync(0xffffffffu, mt0, 2));
        mt1 = fmaxf(mt1, __shfl_xor_sync(0xffffffffu, mt1, 1));
        mt1 = fmaxf(mt1, __shfl_xor_sync(0xffffffffu, mt1, 2));
        const float nm0 = fmaxf(m0, mt0), nm1 = fmaxf(m1, mt1);
        const float corr0 = __expf(m0 - nm0), corr1 = __expf(m1 - nm1);
        m0 = nm0; m1 = nm1;

        float rs0 = 0.f, rs1 = 0.f;
#pragma unroll
        for (int nf = 0; nf < 8; nf++) {
            sacc[nf][0] = __expf(sacc[nf][0] - nm0);
            sacc[nf][1] = __expf(sacc[nf][1] - nm0);
            sacc[nf][2] = __expf(sacc[nf][2] - nm1);
            sacc[nf][3] = __expf(sacc[nf][3] - nm1);
            rs0 += sacc[nf][0] + sacc[nf][1];
            rs1 += sacc[nf][2] + sacc[nf][3];
        }
        rs0 += __shfl_xor_sync(0xffffffffu, rs0, 1);
        rs0 += __shfl_xor_sync(0xffffffffu, rs0, 2);
        rs1 += __shfl_xor_sync(0xffffffffu, rs1, 1);
        rs1 += __shfl_xor_sync(0xffffffffu, rs1, 2);
        l0 = l0 * corr0 + rs0;
        l1 = l1 * corr1 + rs1;
#pragma unroll
        for (int nf = 0; nf < 16; nf++) {
            O[nf][0] *= corr0; O[nf][1] *= corr0;
            O[nf][2] *= corr1; O[nf][3] *= corr1;
        }

#pragma unroll
        for (int kv = 0; kv < 4; kv++) {
            uint32_t ah[4], al[4];
            split2(sacc[2 * kv][0],     sacc[2 * kv][1],     ah[0], al[0]);
            split2(sacc[2 * kv][2],     sacc[2 * kv][3],     ah[1], al[1]);
            split2(sacc[2 * kv + 1][0], sacc[2 * kv + 1][1], ah[2], al[2]);
            split2(sacc[2 * kv + 1][2], sacc[2 * kv + 1][3], ah[3], al[3]);
#pragma unroll
            for (int nf = 0; nf < 16; nf++) {
                uint32_t bb[4];
                LDMX4(bb, base + v_off + nf * 1152 + kv * 32);
                uint32_t bh[2] = {bb[0], bb[1]}, bl[2] = {bb[2], bb[3]};
                MMA4(O[nf], ah, bh);
                MMA4(O[nf], ah, bl);
                MMA4(O[nf], al, bh);
            }
        }
        __syncthreads();
    }

    if (partial) {
        const int slot = ((b * 16 + (qt - 16)) << 1) + part;
        const int lr0 = wq * 16 + qr, lr1 = lr0 + 8;
        if (qc == 0) {
            g_pm[slot][lr0] = m0; g_pl[slot][lr0] = l0;
            g_pm[slot][lr1] = m1; g_pl[slot][lr1] = l1;
        }
#pragma unroll
        for (int nf = 0; nf < 16; nf++) {
            const int col = nf * 8 + qc * 2;
            *(float2*)&g_pO[slot][lr0][col] = make_float2(O[nf][0], O[nf][1]);
            *(float2*)&g_pO[slot][lr1][col] = make_float2(O[nf][2], O[nf][3]);
        }
    } else {
        const float inv0 = 1.f / l0, inv1 = 1.f / l1;
        const size_t row0 = bbase + qb + wq * 16 + qr;
#pragma unroll
        for (int nf = 0; nf < 16; nf++) {
            const int col = nf * 8 + qc * 2;
            uint32_t h, l;
            split2(O[nf][0] * inv0, O[nf][1] * inv0, h, l);
            ((uint32_t*)(g_ctxhi + row0 * DH))[col >> 1] = h;
            ((uint32_t*)(g_ctxlo + row0 * DH))[col >> 1] = l;
            split2(O[nf][2] * inv1, O[nf][3] * inv1, h, l);
            ((uint32_t*)(g_ctxhi + (row0 + 8) * DH))[col >> 1] = h;
            ((uint32_t*)(g_ctxlo + (row0 + 8) * DH))[col >> 1] = l;
        }
    }
}

// combine partials for qt>=16: grid (16, 4), 256 threads.
__global__ void attn_combine() {
    const int qt = 16 + blockIdx.x, b = blockIdx.y;
    const int slotA = ((b * 16 + blockIdx.x) << 1), slotB = slotA + 1;
    const int tid = threadIdx.x;
    const int r = tid >> 2, seg = (tid & 3) * 32;
    const float mA = g_pm[slotA][r], mB = g_pm[slotB][r];
    const float m = fmaxf(mA, mB);
    float wA = __expf(mA - m), wB = __expf(mB - m);
    const float inv = 1.f / (g_pl[slotA][r] * wA + g_pl[slotB][r] * wB);
    wA *= inv; wB *= inv;
    const size_t grow = (size_t)b * SEQ + (size_t)qt * 64 + r;
#pragma unroll
    for (int c = 0; c < 32; c += 2) {
        const int col = seg + c;
        float2 a = *(float2*)&g_pO[slotA][r][col];
        float2 bv = *(float2*)&g_pO[slotB][r][col];
        uint32_t h, l;
        split2(a.x * wA + bv.x * wB, a.y * wA + bv.y * wB, h, l);
        ((uint32_t*)(g_ctxhi + grow * DH))[col >> 1] = h;
        ((uint32_t*)(g_ctxlo + grow * DH))[col >> 1] = l;
    }
}

// ---------------------------------------------------------------------------
extern "C" void kernel_launch(void* const* d_in, const int* in_sizes, int n_in,
                              void* d_out, int out_size)
{
    (void)in_sizes; (void)n_in; (void)out_size;
    const float* x  = (const float*)d_in[0];
    const float* wq = (const float*)d_in[1];
    const float* wk = (const float*)d_in[2];
    const float* wv = (const float*)d_in[3];
    const float* wo = (const float*)d_in[4];
    float* out = (float*)d_out;

    cudaFuncSetAttribute(qkv_mma_kernel,
                         cudaFuncAttributeMaxDynamicSharedMemorySize, QKV_SMEM);
    cudaFuncSetAttribute(out_mma_kernel,
                         cudaFuncAttributeMaxDynamicSharedMemorySize, OUT_SMEM);
    cudaFuncSetAttribute(attn_mma_kernel,
                         cudaFuncAttributeMaxDynamicSharedMemorySize, ATTN_SMEM);

    prep_w_qkv<<<dim3(DM, 3), DH>>>(wq, wk, wv);
    prep_wo<<<DH, 256>>>(wo);
    qkv_mma_kernel<<<dim3(ROWS / 128, 3), 256, QKV_SMEM>>>(x);
    attn_mma_kernel<<<192, 128, ATTN_SMEM>>>();
    attn_combine<<<dim3(16, BATCH), 256>>>();
    out_mma_kernel<<<dim3(ROWS / 64, DM / 128), 256, OUT_SMEM>>>(out);
}

// round 15
// speedup vs baseline: 1.0730x; 1.0730x over previous
#include <cuda_runtime.h>
#include <cuda_bf16.h>
#include <cstdint>

#define BATCH 4
#define SEQ 2048
#define DM 1024
#define DH 128
#define ROWS (BATCH * SEQ)   // 8192

// ---------------------------------------------------------------------------
// Scratch (__device__ globals per allocation rules)
// ---------------------------------------------------------------------------
__device__ __align__(16) float g_v[ROWS * DH];      // V f32 (feeds transpose)
__device__ __align__(16) __nv_bfloat16 g_qhi[ROWS * DH];
__device__ __align__(16) __nv_bfloat16 g_qlo[ROWS * DH];
__device__ __align__(16) __nv_bfloat16 g_khi[ROWS * DH];
__device__ __align__(16) __nv_bfloat16 g_klo[ROWS * DH];
__device__ __align__(16) __nv_bfloat16 g_vthi[BATCH * DH * SEQ];  // [b][d][key]
__device__ __align__(16) __nv_bfloat16 g_vtlo[BATCH * DH * SEQ];
__device__ __align__(16) __nv_bfloat16 g_ctxhi[ROWS * DH];
__device__ __align__(16) __nv_bfloat16 g_ctxlo[ROWS * DH];
// split-K attention partials: slot = b*80 + item (see work mapping)
__device__ __align__(16) float g_pO[320][64][DH];
__device__ float g_pm[320][64];
__device__ float g_pl[320][64];
// transposed bf16 hi/lo weights: wT[z][n][k] = w_z[k][n]
__device__ __align__(16) __nv_bfloat16 g_wThi[3 * DH * DM];
__device__ __align__(16) __nv_bfloat16 g_wTlo[3 * DH * DM];
__device__ __align__(16) __nv_bfloat16 g_woThi[DM * DH];
__device__ __align__(16) __nv_bfloat16 g_woTlo[DM * DH];

// ---------------------------------------------------------------------------
// helpers
// ---------------------------------------------------------------------------
__device__ __forceinline__ uint32_t smem_u32(const void* p) {
    uint32_t a;
    asm("{ .reg .u64 t; cvta.to.shared.u64 t, %1; cvt.u32.u64 %0, t; }"
        : "=r"(a) : "l"(p));
    return a;
}
__device__ __forceinline__ uint32_t pack_bf16x2(float x, float y) {
    __nv_bfloat162 t(__float2bfloat16(x), __float2bfloat16(y));  // x -> low
    return *(uint32_t*)&t;
}
__device__ __forceinline__ void split_bf16(float v, __nv_bfloat16& h, float& lo) {
    h = __float2bfloat16(v);
    lo = v - __bfloat162float(h);
}
__device__ __forceinline__ void split2(float x, float y, uint32_t& hi, uint32_t& lo) {
    __nv_bfloat16 hx, hy; float lx, ly;
    split_bf16(x, hx, lx); split_bf16(y, hy, ly);
    __nv_bfloat162 H(hx, hy);
    hi = *(uint32_t*)&H;
    lo = pack_bf16x2(lx, ly);
}

// mma.sync m16n8k16 bf16 -> f32 (HMMA pipe, target-portable)
#define MMA4(c, a, b) asm volatile( \
    "mma.sync.aligned.m16n8k16.row.col.f32.bf16.bf16.f32 " \
    "{%0,%1,%2,%3}, {%4,%5,%6,%7}, {%8,%9}, {%0,%1,%2,%3};" \
    : "+f"((c)[0]), "+f"((c)[1]), "+f"((c)[2]), "+f"((c)[3]) \
    : "r"((a)[0]), "r"((a)[1]), "r"((a)[2]), "r"((a)[3]), \
      "r"((b)[0]), "r"((b)[1]))

#define LDMX4(d, a) asm volatile( \
    "ldmatrix.sync.aligned.m8n8.x4.shared.b16 {%0,%1,%2,%3}, [%4];" \
    : "=r"((d)[0]), "=r"((d)[1]), "=r"((d)[2]), "=r"((d)[3]) : "r"(a))

#define CP_ASYNC16(dst, src) \
    asm volatile("cp.async.cg.shared.global [%0], [%1], 16;" \
                 :: "r"(dst), "l"(src) : "memory")
#define CP_COMMIT asm volatile("cp.async.commit_group;" ::: "memory")
#define CP_WAIT(n) asm volatile("cp.async.wait_group %0;" :: "n"(n) : "memory")

// ---------------------------------------------------------------------------
// Prep kernels (R12 verbatim)
// ---------------------------------------------------------------------------
__global__ void prep_w_qkv(const float* __restrict__ wq,
                           const float* __restrict__ wk,
                           const float* __restrict__ wv) {
    int k = blockIdx.x, z = blockIdx.y, n = threadIdx.x;   // 128 thr
    const float* w = (z == 0) ? wq : (z == 1) ? wk : wv;
    float v = w[k * DH + n];
    __nv_bfloat16 h; float lo; split_bf16(v, h, lo);
    size_t o = (size_t)z * DH * DM + (size_t)n * DM + k;
    g_wThi[o] = h; g_wTlo[o] = __float2bfloat16(lo);
}
__global__ void prep_wo(const float* __restrict__ wo) {
    int k = blockIdx.x;                                    // 128 blocks, 256 thr
#pragma unroll
    for (int i = 0; i < 4; i++) {
        int n = threadIdx.x + i * 256;
        float v = wo[(size_t)k * DM + n];
        __nv_bfloat16 h; float lo; split_bf16(v, h, lo);
        g_woThi[(size_t)n * DH + k] = h;
        g_woTlo[(size_t)n * DH + k] = __float2bfloat16(lo);
    }
}

// V transpose+split: g_v[b*SEQ+key][d] (f32) -> g_vt{hi,lo}[b][d][key] (bf16)
__global__ void prep_vt() {
    __shared__ float ts[64][132];
    const int b = blockIdx.y, k0 = blockIdx.x * 64;
    const int tid = threadIdx.x;
#pragma unroll
    for (int i = 0; i < 8; i++) {
        int id = tid + i * 256;
        int r = id >> 5, c = (id & 31) * 4;
        float4 v = *(const float4*)&g_v[((size_t)b * SEQ + k0 + r) * DH + c];
        ts[r][c] = v.x; ts[r][c + 1] = v.y; ts[r][c + 2] = v.z; ts[r][c + 3] = v.w;
    }
    __syncthreads();
    const int d = tid >> 1, h = tid & 1;
    uint32_t* ohi = (uint32_t*)g_vthi + ((((size_t)b * DH + d) * SEQ + k0) >> 1) + h * 16;
    uint32_t* olo = (uint32_t*)g_vtlo + ((((size_t)b * DH + d) * SEQ + k0) >> 1) + h * 16;
#pragma unroll
    for (int j = 0; j < 16; j++) {
        int key = h * 32 + j * 2;
        uint32_t hv, lv;
        split2(ts[key][d], ts[key + 1][d], hv, lv);
        ohi[j] = hv; olo[j] = lv;
    }
}

// ---------------------------------------------------------------------------
// Generic warp-mma GEMM core, 3-stage cp.async pipeline (R12 verbatim).
// ---------------------------------------------------------------------------
#define ABY  5120
#define BBY  10240
#define STGB (2 * ABY + 2 * BBY)              // 30720
#define QKV_SMEM (3 * STGB + 2 * 8192)        // 108544
#define OUT_SMEM (3 * STGB)                   // 92160

template <bool SPLIT_A>
__device__ __forceinline__ void gemm_core(
    const float* __restrict__ Af,
    const __nv_bfloat16* __restrict__ Ahi,
    const __nv_bfloat16* __restrict__ Alo, int lda,
    const __nv_bfloat16* __restrict__ Bhig,
    const __nv_bfloat16* __restrict__ Blog, int ldb,
    float* __restrict__ C,
    __nv_bfloat16* __restrict__ Chi, __nv_bfloat16* __restrict__ Clo,
    int ldc, int nc)
{
    extern __shared__ char smg[];
    const uint32_t sbase = smem_u32(smg);
    const int tid  = threadIdx.x;
    const int lane = tid & 31;
    const int wid  = tid >> 5;
    const int warpM = wid >> 2;
    const int warpN = wid & 3;
    const int qr = lane >> 2, qc = lane & 3;

    float acc[2][4][4];
#pragma unroll
    for (int mt = 0; mt < 2; mt++)
#pragma unroll
        for (int nt = 0; nt < 4; nt++)
#pragma unroll
            for (int i = 0; i < 4; i++) acc[mt][nt][i] = 0.f;

    auto issue = [&](int c) {
        const uint32_t bstg = sbase + (c % 3) * STGB + 2 * ABY;
#pragma unroll
        for (int i = 0; i < 4; i++) {
            int u = tid + i * 256;
            int r = u >> 3, cc = u & 3, hf = (u >> 2) & 1;
            CP_ASYNC16(bstg + (hf ? BBY : 0) + r * 80 + cc * 16,
                       (const char*)((hf ? Blog : Bhig) +
                                     (size_t)r * ldb + c * 32 + cc * 8));
        }
        if (SPLIT_A) {
            const uint32_t fstg = sbase + 3 * STGB + (c & 1) * 8192;
#pragma unroll
            for (int i = 0; i < 2; i++) {
                int u = tid + i * 256;
                int r = u >> 3, j = u & 7;
                CP_ASYNC16(fstg + r * 128 + j * 16,
                           (const char*)(Af + (size_t)r * lda + c * 32 + j * 4));
            }
        } else {
            const uint32_t astg = sbase + (c % 3) * STGB;
#pragma unroll
            for (int i = 0; i < 2; i++) {
                int u = tid + i * 256;
                int r = u >> 3, cc = u & 3, hf = (u >> 2) & 1;
                CP_ASYNC16(astg + (hf ? ABY : 0) + r * 80 + cc * 16,
                           (const char*)((hf ? Alo : Ahi) +
                                         (size_t)r * lda + c * 32 + cc * 8));
            }
        }
    };

    issue(0); CP_COMMIT;
    if (nc > 1) { issue(1); CP_COMMIT; }

    const uint32_t aoff_hi = (warpM * 32 + (lane & 15)) * 80 + ((lane >> 4) & 1) * 16;
    const uint32_t aoff_lo = aoff_hi + ABY;
    const uint32_t boff = 2 * ABY + ((lane & 16) ? BBY : 0) +
                          (warpN * 32 + (lane & 7)) * 80 + ((lane >> 3) & 1) * 16;

    for (int c = 0; c < nc; c++) {
        if (c + 1 < nc) CP_WAIT(1); else CP_WAIT(0);
        __syncthreads();

        const uint32_t bufb = sbase + (c % 3) * STGB;
        if (SPLIT_A) {
            const uint32_t fstg = sbase + 3 * STGB + (c & 1) * 8192;
#pragma unroll
            for (int i = 0; i < 2; i++) {
                int u = tid + i * 256;
                int r = u >> 3, j = u & 7;
                float vx, vy, vz, vw;
                asm volatile("ld.shared.v4.f32 {%0,%1,%2,%3}, [%4];"
                             : "=f"(vx), "=f"(vy), "=f"(vz), "=f"(vw)
                             : "r"(fstg + r * 128 + j * 16));
                uint32_t h0, l0, h1, l1;
                split2(vx, vy, h0, l0);
                split2(vz, vw, h1, l1);
                asm volatile("st.shared.v2.b32 [%0], {%1,%2};"
                             :: "r"(bufb + r * 80 + j * 8), "r"(h0), "r"(h1) : "memory");
                asm volatile("st.shared.v2.b32 [%0], {%1,%2};"
                             :: "r"(bufb + ABY + r * 80 + j * 8), "r"(l0), "r"(l1) : "memory");
            }
            __syncthreads();
        }
        if (c + 2 < nc) { issue(c + 2); CP_COMMIT; }

#pragma unroll
        for (int s = 0; s < 2; s++) {
            uint32_t ah[2][4], al[2][4];
#pragma unroll
            for (int mt = 0; mt < 2; mt++) {
                LDMX4(ah[mt], bufb + aoff_hi + mt * 16 * 80 + s * 32);
                LDMX4(al[mt], bufb + aoff_lo + mt * 16 * 80 + s * 32);
            }
#pragma unroll
            for (int nt = 0; nt < 4; nt++) {
                uint32_t bb[4];
                LDMX4(bb, bufb + boff + nt * 8 * 80 + s * 32);
                uint32_t bh[2] = {bb[0], bb[1]}, bl[2] = {bb[2], bb[3]};
#pragma unroll
                for (int mt = 0; mt < 2; mt++) {
                    MMA4(acc[mt][nt], ah[mt], bh);
                    MMA4(acc[mt][nt], ah[mt], bl);
                    MMA4(acc[mt][nt], al[mt], bh);
                }
            }
        }
    }

#pragma unroll
    for (int mt = 0; mt < 2; mt++)
#pragma unroll
        for (int nt = 0; nt < 4; nt++) {
            int r = warpM * 32 + mt * 16 + qr;
            int col = warpN * 32 + nt * 8 + qc * 2;
            if (Chi) {
                uint32_t h0, l0, h1, l1;
                split2(acc[mt][nt][0], acc[mt][nt][1], h0, l0);
                split2(acc[mt][nt][2], acc[mt][nt][3], h1, l1);
                ((uint32_t*)(Chi + (size_t)r * ldc))[col >> 1] = h0;
                ((uint32_t*)(Clo + (size_t)r * ldc))[col >> 1] = l0;
                ((uint32_t*)(Chi + (size_t)(r + 8) * ldc))[col >> 1] = h1;
                ((uint32_t*)(Clo + (size_t)(r + 8) * ldc))[col >> 1] = l1;
            } else {
                *(float2*)(C + (size_t)r * ldc + col) =
                    make_float2(acc[mt][nt][0], acc[mt][nt][1]);
                *(float2*)(C + (size_t)(r + 8) * ldc + col) =
                    make_float2(acc[mt][nt][2], acc[mt][nt][3]);
            }
        }
}

// qkv: grid (128, 3): 64 rows/CTA, K=1024 (nc=32), N=128. A = raw f32 x.
__global__ __launch_bounds__(256, 2) void qkv_mma_kernel(const float* __restrict__ x) {
    const int z = blockIdx.y, bx = blockIdx.x;
    const __nv_bfloat16* Bh = g_wThi + (size_t)z * DH * DM;
    const __nv_bfloat16* Bl = g_wTlo + (size_t)z * DH * DM;
    const size_t rb = (size_t)bx * 64;
    float* C = nullptr; __nv_bfloat16 *Chi = nullptr, *Clo = nullptr;
    if (z == 0)      { Chi = g_qhi + rb * DH; Clo = g_qlo + rb * DH; }
    else if (z == 1) { Chi = g_khi + rb * DH; Clo = g_klo + rb * DH; }
    else             { C = g_v + rb * DH; }
    gemm_core<true>(x + rb * DM, nullptr, nullptr, DM, Bh, Bl, DM, C, Chi, Clo, DH, 32);
}

// out: grid (128, 8): 64 rows, n-slab 128, K=128 (nc=4). A = ctx hi/lo.
__global__ __launch_bounds__(256, 2) void out_mma_kernel(float* __restrict__ out) {
    const int bx = blockIdx.x, by = blockIdx.y;
    const __nv_bfloat16* Bh = g_woThi + (size_t)by * 128 * DH;
    const __nv_bfloat16* Bl = g_woTlo + (size_t)by * 128 * DH;
    float* C = out + (size_t)bx * 64 * DM + by * 128;
    gemm_core<false>(nullptr, g_ctxhi + (size_t)bx * 64 * DH,
                     g_ctxlo + (size_t)bx * 64 * DH, DH,
                     Bh, Bl, DH, C, nullptr, nullptr, DM, 4);
}

// ---------------------------------------------------------------------------
// Tensor-core causal flash attention, fine split-K (<=8 k-tiles per item),
// SINGLE-buffered K/V: smem = 106496 -> 2 CTAs/SM, grid = 320 >= 2*148 so
// every CTA has a co-resident partner hiding load + softmax latency.
// Per batch, 80 items: qt 0-7 x1, 8-15 x2, 16-23 x3, 24-31 x4 parts.
// smem: Qhi@0 (64x272B), Qlo@17408, buf@34816:
//       Khi+0, Klo+17408, Vthi+34816, Vtlo+53248; K stride 272B, Vt 144B.
// ---------------------------------------------------------------------------
#define ATTN_SMEM 106496

__device__ __forceinline__ void attn_issue_tile(
    uint32_t sbase, int tid, int b, int kt, size_t bbase)
{
    const uint32_t base = sbase + 34816;
    const int k0 = kt * 64;
    const char* khi_g = (const char*)(g_khi + (bbase + k0) * DH);
    const char* klo_g = (const char*)(g_klo + (bbase + k0) * DH);
    const char* vhi_g = (const char*)g_vthi + (((size_t)b * DH) * SEQ + k0) * 2;
    const char* vlo_g = (const char*)g_vtlo + (((size_t)b * DH) * SEQ + k0) * 2;
#pragma unroll
    for (int i = 0; i < 8; i++) {
        int id = tid + i * 128;
        int r  = id >> 4, off  = (id & 15) * 16;   // K: 64 rows x 256B
        CP_ASYNC16(base + r * 272 + off, khi_g + (size_t)r * 256 + off);
        CP_ASYNC16(base + 17408 + r * 272 + off, klo_g + (size_t)r * 256 + off);
        int rv = id >> 3, offv = (id & 7) * 16;    // Vt: 128 rows x 128B
        CP_ASYNC16(base + 34816 + rv * 144 + offv,
                   vhi_g + (size_t)rv * (SEQ * 2) + offv);
        CP_ASYNC16(base + 53248 + rv * 144 + offv,
                   vlo_g + (size_t)rv * (SEQ * 2) + offv);
    }
}

__global__ __launch_bounds__(128, 2) void attn_mma_kernel()
{
    extern __shared__ char sm[];
    const uint32_t sbase = smem_u32(sm);
    const int tid  = threadIdx.x;
    const int lane = tid & 31;
    const int wq   = tid >> 5;
    const int qr   = lane >> 2, qc = lane & 3;

    // ---- work-item mapping: bid -> (b, item) -> (qt, part) ----
    const int bid = blockIdx.x;
    const int b = bid / 80;
    const int item = bid % 80;
    int qt, part, nparts;
    if (item < 8)       { qt = item;                   part = 0;        nparts = 1; }
    else if (item < 24) { int j = item - 8;  qt = 8  + (j >> 1); part = j & 1; nparts = 2; }
    else if (item < 48) { int j = item - 24; qt = 16 + j / 3;    part = j % 3; nparts = 3; }
    else                { int j = item - 48; qt = 24 + (j >> 2); part = j & 3; nparts = 4; }
    const int kt0 = part * 8;
    const int kt1 = min(qt, kt0 + 7);
    const bool partial = (nparts > 1);
    const int qb = qt * 64;
    const size_t bbase = (size_t)b * SEQ;
    const int ntiles = kt1 - kt0 + 1;
    const float scale = 0.08838834764831845f;

    {
        const char* qhi_g = (const char*)(g_qhi + (bbase + qb) * DH);
        const char* qlo_g = (const char*)(g_qlo + (bbase + qb) * DH);
#pragma unroll
        for (int i = 0; i < 8; i++) {
            int id = tid + i * 128;
            int r = id >> 4, off = (id & 15) * 16;
            CP_ASYNC16(sbase + r * 272 + off, qhi_g + (size_t)r * 256 + off);
            CP_ASYNC16(sbase + 17408 + r * 272 + off, qlo_g + (size_t)r * 256 + off);
        }
        attn_issue_tile(sbase, tid, b, kt0, bbase);
        CP_COMMIT;
    }

    const uint32_t q_hi_addr = sbase + (wq * 16 + (lane & 15)) * 272 +
                               ((lane >> 4) & 1) * 16;
    const uint32_t q_lo_addr = q_hi_addr + 17408;
    const uint32_t k_off = ((lane & 16) ? 17408u : 0u) +
                           (lane & 7) * 272 + ((lane >> 3) & 1) * 16;
    const uint32_t v_off = 34816u + ((lane & 16) ? 18432u : 0u) +
                           (lane & 7) * 144 + ((lane >> 3) & 1) * 16;
    const uint32_t base = sbase + 34816;

    float O[16][4];
#pragma unroll
    for (int nf = 0; nf < 16; nf++)
#pragma unroll
        for (int i = 0; i < 4; i++) O[nf][i] = 0.f;
    float m0 = -1e30f, m1 = -1e30f, l0 = 0.f, l1 = 0.f;

    for (int t = 0; t < ntiles; t++) {
        const int kt = kt0 + t;
        CP_WAIT(0);
        __syncthreads();

        // ---- S = Q K^T ----
        float sacc[8][4];
#pragma unroll
        for (int nf = 0; nf < 8; nf++)
#pragma unroll
            for (int i = 0; i < 4; i++) sacc[nf][i] = 0.f;

#pragma unroll
        for (int kf = 0; kf < 8; kf++) {
            uint32_t ah[4], al[4];
            LDMX4(ah, q_hi_addr + kf * 32);
            LDMX4(al, q_lo_addr + kf * 32);
#pragma unroll
            for (int nf = 0; nf < 8; nf++) {
                uint32_t bb[4];
                LDMX4(bb, base + k_off + nf * 2176 + kf * 32);
                uint32_t bh[2] = {bb[0], bb[1]}, bl[2] = {bb[2], bb[3]};
                MMA4(sacc[nf], ah, bh);
                MMA4(sacc[nf], ah, bl);
                MMA4(sacc[nf], al, bh);
            }
        }

        // ---- scale + causal mask ----
#pragma unroll
        for (int nf = 0; nf < 8; nf++)
#pragma unroll
            for (int i = 0; i < 4; i++) sacc[nf][i] *= scale;
        if (kt == qt) {
            const int q0 = wq * 16 + qr, q1 = q0 + 8;
#pragma unroll
            for (int nf = 0; nf < 8; nf++) {
                const int key = nf * 8 + qc * 2;
                if (key > q0)     sacc[nf][0] = -1e30f;
                if (key + 1 > q0) sacc[nf][1] = -1e30f;
                if (key > q1)     sacc[nf][2] = -1e30f;
                if (key + 1 > q1) sacc[nf][3] = -1e30f;
            }
        }

        // ---- online softmax ----
        float mt0 = -1e30f, mt1 = -1e30f;
#pragma unroll
        for (int nf = 0; nf < 8; nf++) {
            mt0 = fmaxf(mt0, fmaxf(sacc[nf][0], sacc[nf][1]));
            mt1 = fmaxf(mt1, fmaxf(sacc[nf][2], sacc[nf][3]));
        }
        mt0 = fmaxf(mt0, __shfl_xor_sync(0xffffffffu, mt0, 1));
        mt0 = fmaxf(mt0, __shfl_xor_sync(0xffffffffu, mt0, 2));
        mt1 = fmaxf(mt1, __shfl_xor_sync(0xffffffffu, mt1, 1));
        mt1 = fmaxf(mt1, __shfl_xor_sync(0xffffffffu, mt1, 2));
        const float nm0 = fmaxf(m0, mt0), nm1 = fmaxf(m1, mt1);
        const float corr0 = __expf(m0 - nm0), corr1 = __expf(m1 - nm1);
        m0 = nm0; m1 = nm1;

        float rs0 = 0.f, rs1 = 0.f;
#pragma unroll
        for (int nf = 0; nf < 8; nf++) {
            sacc[nf][0] = __expf(sacc[nf][0] - nm0);
            sacc[nf][1] = __expf(sacc[nf][1] - nm0);
            sacc[nf][2] = __expf(sacc[nf][2] - nm1);
            sacc[nf][3] = __expf(sacc[nf][3] - nm1);
            rs0 += sacc[nf][0] + sacc[nf][1];
            rs1 += sacc[nf][2] + sacc[nf][3];
        }
        rs0 += __shfl_xor_sync(0xffffffffu, rs0, 1);
        rs0 += __shfl_xor_sync(0xffffffffu, rs0, 2);
        rs1 += __shfl_xor_sync(0xffffffffu, rs1, 1);
        rs1 += __shfl_xor_sync(0xffffffffu, rs1, 2);
        l0 = l0 * corr0 + rs0;
        l1 = l1 * corr1 + rs1;
#pragma unroll
        for (int nf = 0; nf < 16; nf++) {
            O[nf][0] *= corr0; O[nf][1] *= corr0;
            O[nf][2] *= corr1; O[nf][3] *= corr1;
        }

        // ---- O += P V ----
#pragma unroll
        for (int kv = 0; kv < 4; kv++) {
            uint32_t ah[4], al[4];
            split2(sacc[2 * kv][0],     sacc[2 * kv][1],     ah[0], al[0]);
            split2(sacc[2 * kv][2],     sacc[2 * kv][3],     ah[1], al[1]);
            split2(sacc[2 * kv + 1][0], sacc[2 * kv + 1][1], ah[2], al[2]);
            split2(sacc[2 * kv + 1][2], sacc[2 * kv + 1][3], ah[3], al[3]);
#pragma unroll
            for (int nf = 0; nf < 16; nf++) {
                uint32_t bb[4];
                LDMX4(bb, base + v_off + nf * 1152 + kv * 32);
                uint32_t bh[2] = {bb[0], bb[1]}, bl[2] = {bb[2], bb[3]};
                MMA4(O[nf], ah, bh);
                MMA4(O[nf], ah, bl);
                MMA4(O[nf], al, bh);
            }
        }

        if (t + 1 < ntiles) {
            __syncthreads();   // all warps done reading buffer
            attn_issue_tile(sbase, tid, b, kt + 1, bbase);
            CP_COMMIT;
        }
    }

    if (partial) {
        const int slot = b * 80 + item;
        const int lr0 = wq * 16 + qr, lr1 = lr0 + 8;
        if (qc == 0) {
            g_pm[slot][lr0] = m0; g_pl[slot][lr0] = l0;
            g_pm[slot][lr1] = m1; g_pl[slot][lr1] = l1;
        }
#pragma unroll
        for (int nf = 0; nf < 16; nf++) {
            const int col = nf * 8 + qc * 2;
            *(float2*)&g_pO[slot][lr0][col] = make_float2(O[nf][0], O[nf][1]);
            *(float2*)&g_pO[slot][lr1][col] = make_float2(O[nf][2], O[nf][3]);
        }
    } else {
        const float inv0 = 1.f / l0, inv1 = 1.f / l1;
        const size_t row0 = bbase + qb + wq * 16 + qr;
#pragma unroll
        for (int nf = 0; nf < 16; nf++) {
            const int col = nf * 8 + qc * 2;
            uint32_t h, l;
            split2(O[nf][0] * inv0, O[nf][1] * inv0, h, l);
            ((uint32_t*)(g_ctxhi + row0 * DH))[col >> 1] = h;
            ((uint32_t*)(g_ctxlo + row0 * DH))[col >> 1] = l;
            split2(O[nf][2] * inv1, O[nf][3] * inv1, h, l);
            ((uint32_t*)(g_ctxhi + (row0 + 8) * DH))[col >> 1] = h;
            ((uint32_t*)(g_ctxlo + (row0 + 8) * DH))[col >> 1] = l;
        }
    }
}

// combine partials for qt>=8: grid (24, 4), 256 threads (r = tid/4, 32-col seg).
__global__ void attn_combine() {
    const int qt = 8 + blockIdx.x, b = blockIdx.y;
    const int nparts = (qt + 8) >> 3;             // ceil((qt+1)/8)
    int base_i;
    if (qt < 16)      base_i = 8  + (qt - 8)  * 2;
    else if (qt < 24) base_i = 24 + (qt - 16) * 3;
    else              base_i = 48 + (qt - 24) * 4;
    const int slot0 = b * 80 + base_i;
    const int tid = threadIdx.x;
    const int r = tid >> 2, seg = (tid & 3) * 32;

    float m = -1e30f;
    for (int p = 0; p < nparts; p++) m = fmaxf(m, g_pm[slot0 + p][r]);
    float w[4];
    float l = 0.f;
    for (int p = 0; p < nparts; p++) {
        w[p] = __expf(g_pm[slot0 + p][r] - m);
        l += g_pl[slot0 + p][r] * w[p];
    }
    const float inv = 1.f / l;
    const size_t grow = (size_t)b * SEQ + (size_t)qt * 64 + r;
#pragma unroll 4
    for (int c = 0; c < 32; c += 2) {
        const int col = seg + c;
        float ax = 0.f, ay = 0.f;
        for (int p = 0; p < nparts; p++) {
            float2 v = *(float2*)&g_pO[slot0 + p][r][col];
            ax += v.x * w[p]; ay += v.y * w[p];
        }
        uint32_t h, l2;
        split2(ax * inv, ay * inv, h, l2);
        ((uint32_t*)(g_ctxhi + grow * DH))[col >> 1] = h;
        ((uint32_t*)(g_ctxlo + grow * DH))[col >> 1] = l2;
    }
}

// ---------------------------------------------------------------------------
extern "C" void kernel_launch(void* const* d_in, const int* in_sizes, int n_in,
                              void* d_out, int out_size)
{
    (void)in_sizes; (void)n_in; (void)out_size;
    const float* x  = (const float*)d_in[0];
    const float* wq = (const float*)d_in[1];
    const float* wk = (const float*)d_in[2];
    const float* wv = (const float*)d_in[3];
    const float* wo = (const float*)d_in[4];
    float* out = (float*)d_out;

    cudaFuncSetAttribute(qkv_mma_kernel,
                         cudaFuncAttributeMaxDynamicSharedMemorySize, QKV_SMEM);
    cudaFuncSetAttribute(out_mma_kernel,
                         cudaFuncAttributeMaxDynamicSharedMemorySize, OUT_SMEM);
    cudaFuncSetAttribute(attn_mma_kernel,
                         cudaFuncAttributeMaxDynamicSharedMemorySize, ATTN_SMEM);

    prep_w_qkv<<<dim3(DM, 3), DH>>>(wq, wk, wv);
    prep_wo<<<DH, 256>>>(wo);
    qkv_mma_kernel<<<dim3(ROWS / 64, 3), 256, QKV_SMEM>>>(x);
    prep_vt<<<dim3(SEQ / 64, BATCH), 256>>>();
    attn_mma_kernel<<<BATCH * 80, 128, ATTN_SMEM>>>();
    attn_combine<<<dim3(24, BATCH), 256>>>();
    out_mma_kernel<<<dim3(ROWS / 64, DM / 128), 256, OUT_SMEM>>>(out);
}

// round 16
// speedup vs baseline: 1.1240x; 1.0475x over previous
#include <cuda_runtime.h>
#include <cuda_bf16.h>
#include <cstdint>

#define BATCH 4
#define SEQ 2048
#define DM 1024
#define DH 128
#define ROWS (BATCH * SEQ)   // 8192

// ---------------------------------------------------------------------------
// Scratch (__device__ globals per allocation rules)
// ---------------------------------------------------------------------------
__device__ __align__(16) float g_v[ROWS * DH];      // V f32 (feeds transpose)
__device__ __align__(16) __nv_bfloat16 g_qhi[ROWS * DH];
__device__ __align__(16) __nv_bfloat16 g_qlo[ROWS * DH];
__device__ __align__(16) __nv_bfloat16 g_khi[ROWS * DH];
__device__ __align__(16) __nv_bfloat16 g_klo[ROWS * DH];
__device__ __align__(16) __nv_bfloat16 g_vthi[BATCH * DH * SEQ];  // [b][d][key]
__device__ __align__(16) __nv_bfloat16 g_vtlo[BATCH * DH * SEQ];
__device__ __align__(16) __nv_bfloat16 g_ctxhi[ROWS * DH];
__device__ __align__(16) __nv_bfloat16 g_ctxlo[ROWS * DH];
// split-K attention partials: slot = (b*16 + qt-16)*2 + part
__device__ __align__(16) float g_pO[128][64][DH];
__device__ float g_pm[128][64];
__device__ float g_pl[128][64];
// transposed bf16 hi/lo weights: wT[z][n][k] = w_z[k][n]
__device__ __align__(16) __nv_bfloat16 g_wThi[3 * DH * DM];
__device__ __align__(16) __nv_bfloat16 g_wTlo[3 * DH * DM];
__device__ __align__(16) __nv_bfloat16 g_woThi[DM * DH];
__device__ __align__(16) __nv_bfloat16 g_woTlo[DM * DH];

// ---------------------------------------------------------------------------
// helpers
// ---------------------------------------------------------------------------
__device__ __forceinline__ uint32_t smem_u32(const void* p) {
    uint32_t a;
    asm("{ .reg .u64 t; cvta.to.shared.u64 t, %1; cvt.u32.u64 %0, t; }"
        : "=r"(a) : "l"(p));
    return a;
}
__device__ __forceinline__ uint32_t pack_bf16x2(float x, float y) {
    __nv_bfloat162 t(__float2bfloat16(x), __float2bfloat16(y));  // x -> low
    return *(uint32_t*)&t;
}
__device__ __forceinline__ void split_bf16(float v, __nv_bfloat16& h, float& lo) {
    h = __float2bfloat16(v);
    lo = v - __bfloat162float(h);
}
__device__ __forceinline__ void split2(float x, float y, uint32_t& hi, uint32_t& lo) {
    __nv_bfloat16 hx, hy; float lx, ly;
    split_bf16(x, hx, lx); split_bf16(y, hy, ly);
    __nv_bfloat162 H(hx, hy);
    hi = *(uint32_t*)&H;
    lo = pack_bf16x2(lx, ly);
}

// mma.sync m16n8k16 bf16 -> f32 (HMMA pipe, target-portable)
#define MMA4(c, a, b) asm volatile( \
    "mma.sync.aligned.m16n8k16.row.col.f32.bf16.bf16.f32 " \
    "{%0,%1,%2,%3}, {%4,%5,%6,%7}, {%8,%9}, {%0,%1,%2,%3};" \
    : "+f"((c)[0]), "+f"((c)[1]), "+f"((c)[2]), "+f"((c)[3]) \
    : "r"((a)[0]), "r"((a)[1]), "r"((a)[2]), "r"((a)[3]), \
      "r"((b)[0]), "r"((b)[1]))

#define LDMX4(d, a) asm volatile( \
    "ldmatrix.sync.aligned.m8n8.x4.shared.b16 {%0,%1,%2,%3}, [%4];" \
    : "=r"((d)[0]), "=r"((d)[1]), "=r"((d)[2]), "=r"((d)[3]) : "r"(a))

#define CP_ASYNC16(dst, src) \
    asm volatile("cp.async.cg.shared.global [%0], [%1], 16;" \
                 :: "r"(dst), "l"(src) : "memory")
#define CP_COMMIT asm volatile("cp.async.commit_group;" ::: "memory")
#define CP_WAIT(n) asm volatile("cp.async.wait_group %0;" :: "n"(n) : "memory")

// ---------------------------------------------------------------------------
// Prep kernels (R12 verbatim)
// ---------------------------------------------------------------------------
__global__ void prep_w_qkv(const float* __restrict__ wq,
                           const float* __restrict__ wk,
                           const float* __restrict__ wv) {
    int k = blockIdx.x, z = blockIdx.y, n = threadIdx.x;   // 128 thr
    const float* w = (z == 0) ? wq : (z == 1) ? wk : wv;
    float v = w[k * DH + n];
    __nv_bfloat16 h; float lo; split_bf16(v, h, lo);
    size_t o = (size_t)z * DH * DM + (size_t)n * DM + k;
    g_wThi[o] = h; g_wTlo[o] = __float2bfloat16(lo);
}
__global__ void prep_wo(const float* __restrict__ wo) {
    int k = blockIdx.x;                                    // 128 blocks, 256 thr
#pragma unroll
    for (int i = 0; i < 4; i++) {
        int n = threadIdx.x + i * 256;
        float v = wo[(size_t)k * DM + n];
        __nv_bfloat16 h; float lo; split_bf16(v, h, lo);
        g_woThi[(size_t)n * DH + k] = h;
        g_woTlo[(size_t)n * DH + k] = __float2bfloat16(lo);
    }
}

// V transpose+split: g_v[b*SEQ+key][d] (f32) -> g_vt{hi,lo}[b][d][key] (bf16)
__global__ void prep_vt() {
    __shared__ float ts[64][132];
    const int b = blockIdx.y, k0 = blockIdx.x * 64;
    const int tid = threadIdx.x;
#pragma unroll
    for (int i = 0; i < 8; i++) {
        int id = tid + i * 256;
        int r = id >> 5, c = (id & 31) * 4;
        float4 v = *(const float4*)&g_v[((size_t)b * SEQ + k0 + r) * DH + c];
        ts[r][c] = v.x; ts[r][c + 1] = v.y; ts[r][c + 2] = v.z; ts[r][c + 3] = v.w;
    }
    __syncthreads();
    const int d = tid >> 1, h = tid & 1;
    uint32_t* ohi = (uint32_t*)g_vthi + ((((size_t)b * DH + d) * SEQ + k0) >> 1) + h * 16;
    uint32_t* olo = (uint32_t*)g_vtlo + ((((size_t)b * DH + d) * SEQ + k0) >> 1) + h * 16;
#pragma unroll
    for (int j = 0; j < 16; j++) {
        int key = h * 32 + j * 2;
        uint32_t hv, lv;
        split2(ts[key][d], ts[key + 1][d], hv, lv);
        ohi[j] = hv; olo[j] = lv;
    }
}

// ---------------------------------------------------------------------------
// Generic warp-mma GEMM core, 3-stage cp.async pipeline (R12 verbatim).
// ---------------------------------------------------------------------------
#define ABY  5120
#define BBY  10240
#define STGB (2 * ABY + 2 * BBY)              // 30720
#define QKV_SMEM (3 * STGB + 2 * 8192)        // 108544
#define OUT_SMEM (3 * STGB)                   // 92160

template <bool SPLIT_A>
__device__ __forceinline__ void gemm_core(
    const float* __restrict__ Af,
    const __nv_bfloat16* __restrict__ Ahi,
    const __nv_bfloat16* __restrict__ Alo, int lda,
    const __nv_bfloat16* __restrict__ Bhig,
    const __nv_bfloat16* __restrict__ Blog, int ldb,
    float* __restrict__ C,
    __nv_bfloat16* __restrict__ Chi, __nv_bfloat16* __restrict__ Clo,
    int ldc, int nc)
{
    extern __shared__ char smg[];
    const uint32_t sbase = smem_u32(smg);
    const int tid  = threadIdx.x;
    const int lane = tid & 31;
    const int wid  = tid >> 5;
    const int warpM = wid >> 2;
    const int warpN = wid & 3;
    const int qr = lane >> 2, qc = lane & 3;

    float acc[2][4][4];
#pragma unroll
    for (int mt = 0; mt < 2; mt++)
#pragma unroll
        for (int nt = 0; nt < 4; nt++)
#pragma unroll
            for (int i = 0; i < 4; i++) acc[mt][nt][i] = 0.f;

    auto issue = [&](int c) {
        const uint32_t bstg = sbase + (c % 3) * STGB + 2 * ABY;
#pragma unroll
        for (int i = 0; i < 4; i++) {
            int u = tid + i * 256;
            int r = u >> 3, cc = u & 3, hf = (u >> 2) & 1;
            CP_ASYNC16(bstg + (hf ? BBY : 0) + r * 80 + cc * 16,
                       (const char*)((hf ? Blog : Bhig) +
                                     (size_t)r * ldb + c * 32 + cc * 8));
        }
        if (SPLIT_A) {
            const uint32_t fstg = sbase + 3 * STGB + (c & 1) * 8192;
#pragma unroll
            for (int i = 0; i < 2; i++) {
                int u = tid + i * 256;
                int r = u >> 3, j = u & 7;
                CP_ASYNC16(fstg + r * 128 + j * 16,
                           (const char*)(Af + (size_t)r * lda + c * 32 + j * 4));
            }
        } else {
            const uint32_t astg = sbase + (c % 3) * STGB;
#pragma unroll
            for (int i = 0; i < 2; i++) {
                int u = tid + i * 256;
                int r = u >> 3, cc = u & 3, hf = (u >> 2) & 1;
                CP_ASYNC16(astg + (hf ? ABY : 0) + r * 80 + cc * 16,
                           (const char*)((hf ? Alo : Ahi) +
                                         (size_t)r * lda + c * 32 + cc * 8));
            }
        }
    };

    issue(0); CP_COMMIT;
    if (nc > 1) { issue(1); CP_COMMIT; }

    const uint32_t aoff_hi = (warpM * 32 + (lane & 15)) * 80 + ((lane >> 4) & 1) * 16;
    const uint32_t aoff_lo = aoff_hi + ABY;
    const uint32_t boff = 2 * ABY + ((lane & 16) ? BBY : 0) +
                          (warpN * 32 + (lane & 7)) * 80 + ((lane >> 3) & 1) * 16;

    for (int c = 0; c < nc; c++) {
        if (c + 1 < nc) CP_WAIT(1); else CP_WAIT(0);
        __syncthreads();

        const uint32_t bufb = sbase + (c % 3) * STGB;
        if (SPLIT_A) {
            const uint32_t fstg = sbase + 3 * STGB + (c & 1) * 8192;
#pragma unroll
            for (int i = 0; i < 2; i++) {
                int u = tid + i * 256;
                int r = u >> 3, j = u & 7;
                float vx, vy, vz, vw;
                asm volatile("ld.shared.v4.f32 {%0,%1,%2,%3}, [%4];"
                             : "=f"(vx), "=f"(vy), "=f"(vz), "=f"(vw)
                             : "r"(fstg + r * 128 + j * 16));
                uint32_t h0, l0, h1, l1;
                split2(vx, vy, h0, l0);
                split2(vz, vw, h1, l1);
                asm volatile("st.shared.v2.b32 [%0], {%1,%2};"
                             :: "r"(bufb + r * 80 + j * 8), "r"(h0), "r"(h1) : "memory");
                asm volatile("st.shared.v2.b32 [%0], {%1,%2};"
                             :: "r"(bufb + ABY + r * 80 + j * 8), "r"(l0), "r"(l1) : "memory");
            }
            __syncthreads();
        }
        if (c + 2 < nc) { issue(c + 2); CP_COMMIT; }

#pragma unroll
        for (int s = 0; s < 2; s++) {
            uint32_t ah[2][4], al[2][4];
#pragma unroll
            for (int mt = 0; mt < 2; mt++) {
                LDMX4(ah[mt], bufb + aoff_hi + mt * 16 * 80 + s * 32);
                LDMX4(al[mt], bufb + aoff_lo + mt * 16 * 80 + s * 32);
            }
#pragma unroll
            for (int nt = 0; nt < 4; nt++) {
                uint32_t bb[4];
                LDMX4(bb, bufb + boff + nt * 8 * 80 + s * 32);
                uint32_t bh[2] = {bb[0], bb[1]}, bl[2] = {bb[2], bb[3]};
#pragma unroll
                for (int mt = 0; mt < 2; mt++) {
                    MMA4(acc[mt][nt], ah[mt], bh);
                    MMA4(acc[mt][nt], ah[mt], bl);
                    MMA4(acc[mt][nt], al[mt], bh);
                }
            }
        }
    }

#pragma unroll
    for (int mt = 0; mt < 2; mt++)
#pragma unroll
        for (int nt = 0; nt < 4; nt++) {
            int r = warpM * 32 + mt * 16 + qr;
            int col = warpN * 32 + nt * 8 + qc * 2;
            if (Chi) {
                uint32_t h0, l0, h1, l1;
                split2(acc[mt][nt][0], acc[mt][nt][1], h0, l0);
                split2(acc[mt][nt][2], acc[mt][nt][3], h1, l1);
                ((uint32_t*)(Chi + (size_t)r * ldc))[col >> 1] = h0;
                ((uint32_t*)(Clo + (size_t)r * ldc))[col >> 1] = l0;
                ((uint32_t*)(Chi + (size_t)(r + 8) * ldc))[col >> 1] = h1;
                ((uint32_t*)(Clo + (size_t)(r + 8) * ldc))[col >> 1] = l1;
            } else {
                *(float2*)(C + (size_t)r * ldc + col) =
                    make_float2(acc[mt][nt][0], acc[mt][nt][1]);
                *(float2*)(C + (size_t)(r + 8) * ldc + col) =
                    make_float2(acc[mt][nt][2], acc[mt][nt][3]);
            }
        }
}

// qkv: grid (128, 3): 64 rows/CTA, K=1024 (nc=32), N=128. A = raw f32 x.
__global__ __launch_bounds__(256, 2) void qkv_mma_kernel(const float* __restrict__ x) {
    const int z = blockIdx.y, bx = blockIdx.x;
    const __nv_bfloat16* Bh = g_wThi + (size_t)z * DH * DM;
    const __nv_bfloat16* Bl = g_wTlo + (size_t)z * DH * DM;
    const size_t rb = (size_t)bx * 64;
    float* C = nullptr; __nv_bfloat16 *Chi = nullptr, *Clo = nullptr;
    if (z == 0)      { Chi = g_qhi + rb * DH; Clo = g_qlo + rb * DH; }
    else if (z == 1) { Chi = g_khi + rb * DH; Clo = g_klo + rb * DH; }
    else             { C = g_v + rb * DH; }
    gemm_core<true>(x + rb * DM, nullptr, nullptr, DM, Bh, Bl, DM, C, Chi, Clo, DH, 32);
}

// out: grid (128, 8): 64 rows, n-slab 128, K=128 (nc=4). A = ctx hi/lo.
__global__ __launch_bounds__(256, 2) void out_mma_kernel(float* __restrict__ out) {
    const int bx = blockIdx.x, by = blockIdx.y;
    const __nv_bfloat16* Bh = g_woThi + (size_t)by * 128 * DH;
    const __nv_bfloat16* Bl = g_woTlo + (size_t)by * 128 * DH;
    float* C = out + (size_t)bx * 64 * DM + by * 128;
    gemm_core<false>(nullptr, g_ctxhi + (size_t)bx * 64 * DH,
                     g_ctxlo + (size_t)bx * 64 * DH, DH,
                     Bh, Bl, DH, C, nullptr, nullptr, DM, 4);
}

// ---------------------------------------------------------------------------
// Tensor-core causal flash attention, split-K (R12 grid=192 mapping),
// DOUBLE-buffered, now 8 warps (256 thr): warp pair (w, w+4) shares q rows;
// w takes keys 0-31, w+4 keys 32-63 of each tile, each with an independent
// online softmax; halves merged in smem at the end (same math as combine).
// 2 warps/SMSP hide softmax + ldmatrix latency behind partner HMMAs.
// smem: Qhi@0 (64x272B), Qlo@17408, buf p @34816+p*71680:
//       Khi+0, Klo+17408, Vthi+34816, Vtlo+53248; K stride 272B, Vt 144B.
// End merge reuses Q area: Osm 64x132 f32 @0, stats @33792.
// ---------------------------------------------------------------------------
#define ATTN_SMEM 178176

__device__ __forceinline__ void attn_issue_tile(
    uint32_t sbase, int tid, int b, int kt, int p, size_t bbase)
{
    const uint32_t base = sbase + 34816 + p * 71680;
    const int k0 = kt * 64;
    const char* khi_g = (const char*)(g_khi + (bbase + k0) * DH);
    const char* klo_g = (const char*)(g_klo + (bbase + k0) * DH);
    const char* vhi_g = (const char*)g_vthi + (((size_t)b * DH) * SEQ + k0) * 2;
    const char* vlo_g = (const char*)g_vtlo + (((size_t)b * DH) * SEQ + k0) * 2;
#pragma unroll
    for (int i = 0; i < 4; i++) {
        int id = tid + i * 256;
        int r  = id >> 4, off  = (id & 15) * 16;   // K: 64 rows x 256B
        CP_ASYNC16(base + r * 272 + off, khi_g + (size_t)r * 256 + off);
        CP_ASYNC16(base + 17408 + r * 272 + off, klo_g + (size_t)r * 256 + off);
        int rv = id >> 3, offv = (id & 7) * 16;    // Vt: 128 rows x 128B
        CP_ASYNC16(base + 34816 + rv * 144 + offv,
                   vhi_g + (size_t)rv * (SEQ * 2) + offv);
        CP_ASYNC16(base + 53248 + rv * 144 + offv,
                   vlo_g + (size_t)rv * (SEQ * 2) + offv);
    }
}

__global__ __launch_bounds__(256, 1) void attn_mma_kernel()
{
    extern __shared__ char sm[];
    const uint32_t sbase = smem_u32(sm);
    const int tid  = threadIdx.x;
    const int lane = tid & 31;
    const int wid  = tid >> 5;
    const int wq   = wid & 3;        // q-row group
    const int half = wid >> 2;       // key half (0: keys 0-31, 1: keys 32-63)
    const int qr   = lane >> 2, qc = lane & 3;

    const int bid = blockIdx.x;
    int b, qt, kt0, kt1, part;
    bool partial;
    if (bid < 64) {
        b = bid & 3; qt = 16 + (bid >> 2); kt0 = 0; kt1 = 15;
        partial = true; part = 0;
    } else if (bid < 128) {
        int i = bid - 64;
        b = i & 3; qt = 31 - (i >> 2); kt0 = 16; kt1 = qt;
        partial = true; part = 1;
    } else {
        int i = bid - 128;
        b = i & 3; qt = 15 - (i >> 2); kt0 = 0; kt1 = qt;
        partial = false; part = 0;
    }
    const int qb = qt * 64;
    const size_t bbase = (size_t)b * SEQ;
    const int ntiles = kt1 - kt0 + 1;
    const float scale = 0.08838834764831845f;

    {
        const char* qhi_g = (const char*)(g_qhi + (bbase + qb) * DH);
        const char* qlo_g = (const char*)(g_qlo + (bbase + qb) * DH);
#pragma unroll
        for (int i = 0; i < 4; i++) {
            int id = tid + i * 256;
            int r = id >> 4, off = (id & 15) * 16;
            CP_ASYNC16(sbase + r * 272 + off, qhi_g + (size_t)r * 256 + off);
            CP_ASYNC16(sbase + 17408 + r * 272 + off, qlo_g + (size_t)r * 256 + off);
        }
        attn_issue_tile(sbase, tid, b, kt0, 0, bbase);
        CP_COMMIT;
    }

    const uint32_t q_hi_addr = sbase + (wq * 16 + (lane & 15)) * 272 +
                               ((lane >> 4) & 1) * 16;
    const uint32_t q_lo_addr = q_hi_addr + 17408;
    // K fragment: rows half*32 + nf*8 + (lane&7)
    const uint32_t k_off = half * 8704 + ((lane & 16) ? 17408u : 0u) +
                           (lane & 7) * 272 + ((lane >> 3) & 1) * 16;
    // V fragment: byte col = half*64 + kv*32 + ((lane>>3)&1)*16
    const uint32_t v_off = 34816u + ((lane & 16) ? 18432u : 0u) +
                           (lane & 7) * 144 + half * 64 + ((lane >> 3) & 1) * 16;

    float O[16][4];
#pragma unroll
    for (int nf = 0; nf < 16; nf++)
#pragma unroll
        for (int i = 0; i < 4; i++) O[nf][i] = 0.f;
    float m0 = -1e30f, m1 = -1e30f, l0 = 0.f, l1 = 0.f;

    for (int t = 0; t < ntiles; t++) {
        const int kt = kt0 + t;
        const int p = t & 1;
        if (t + 1 < ntiles) {
            attn_issue_tile(sbase, tid, b, kt + 1, p ^ 1, bbase);
            CP_COMMIT;
            CP_WAIT(1);
        } else {
            CP_WAIT(0);
        }
        __syncthreads();

        const uint32_t base = sbase + 34816 + p * 71680;

        // ---- S = Q K^T (this warp's 32-key half) ----
        float sacc[4][4];
#pragma unroll
        for (int nf = 0; nf < 4; nf++)
#pragma unroll
            for (int i = 0; i < 4; i++) sacc[nf][i] = 0.f;

#pragma unroll
        for (int kf = 0; kf < 8; kf++) {
            uint32_t ah[4], al[4];
            LDMX4(ah, q_hi_addr + kf * 32);
            LDMX4(al, q_lo_addr + kf * 32);
#pragma unroll
            for (int nf = 0; nf < 4; nf++) {
                uint32_t bb[4];
                LDMX4(bb, base + k_off + nf * 2176 + kf * 32);
                uint32_t bh[2] = {bb[0], bb[1]}, bl[2] = {bb[2], bb[3]};
                MMA4(sacc[nf], ah, bh);
                MMA4(sacc[nf], ah, bl);
                MMA4(sacc[nf], al, bh);
            }
        }

        // ---- scale + causal mask (diagonal tile only) ----
#pragma unroll
        for (int nf = 0; nf < 4; nf++)
#pragma unroll
            for (int i = 0; i < 4; i++) sacc[nf][i] *= scale;
        if (kt == qt) {
            const int q0 = wq * 16 + qr, q1 = q0 + 8;
#pragma unroll
            for (int nf = 0; nf < 4; nf++) {
                const int key = half * 32 + nf * 8 + qc * 2;
                if (key > q0)     sacc[nf][0] = -1e30f;
                if (key + 1 > q0) sacc[nf][1] = -1e30f;
                if (key > q1)     sacc[nf][2] = -1e30f;
                if (key + 1 > q1) sacc[nf][3] = -1e30f;
            }
        }

        // ---- independent online softmax over this half's keys ----
        float mt0 = -1e30f, mt1 = -1e30f;
#pragma unroll
        for (int nf = 0; nf < 4; nf++) {
            mt0 = fmaxf(mt0, fmaxf(sacc[nf][0], sacc[nf][1]));
            mt1 = fmaxf(mt1, fmaxf(sacc[nf][2], sacc[nf][3]));
        }
        mt0 = fmaxf(mt0, __shfl_xor_sync(0xffffffffu, mt0, 1));
        mt0 = fmaxf(mt0, __shfl_xor_sync(0xffffffffu, mt0, 2));
        mt1 = fmaxf(mt1, __shfl_xor_sync(0xffffffffu, mt1, 1));
        mt1 = fmaxf(mt1, __shfl_xor_sync(0xffffffffu, mt1, 2));
        // clamp keeps exp() well-defined when a half has no valid keys yet
        const float nm0 = fmaxf(fmaxf(m0, mt0), -1e4f);
        const float nm1 = fmaxf(fmaxf(m1, mt1), -1e4f);
        const float corr0 = __expf(m0 - nm0), corr1 = __expf(m1 - nm1);
        m0 = nm0; m1 = nm1;

        float rs0 = 0.f, rs1 = 0.f;
#pragma unroll
        for (int nf = 0; nf < 4; nf++) {
            sacc[nf][0] = __expf(sacc[nf][0] - nm0);
            sacc[nf][1] = __expf(sacc[nf][1] - nm0);
            sacc[nf][2] = __expf(sacc[nf][2] - nm1);
            sacc[nf][3] = __expf(sacc[nf][3] - nm1);
            rs0 += sacc[nf][0] + sacc[nf][1];
            rs1 += sacc[nf][2] + sacc[nf][3];
        }
        rs0 += __shfl_xor_sync(0xffffffffu, rs0, 1);
        rs0 += __shfl_xor_sync(0xffffffffu, rs0, 2);
        rs1 += __shfl_xor_sync(0xffffffffu, rs1, 1);
        rs1 += __shfl_xor_sync(0xffffffffu, rs1, 2);
        l0 = l0 * corr0 + rs0;
        l1 = l1 * corr1 + rs1;
#pragma unroll
        for (int nf = 0; nf < 16; nf++) {
            O[nf][0] *= corr0; O[nf][1] *= corr0;
            O[nf][2] *= corr1; O[nf][3] *= corr1;
        }

        // ---- O += P V over this half's 32 keys (full d) ----
#pragma unroll
        for (int kv = 0; kv < 2; kv++) {
            uint32_t ah[4], al[4];
            split2(sacc[2 * kv][0],     sacc[2 * kv][1],     ah[0], al[0]);
            split2(sacc[2 * kv][2],     sacc[2 * kv][3],     ah[1], al[1]);
            split2(sacc[2 * kv + 1][0], sacc[2 * kv + 1][1], ah[2], al[2]);
            split2(sacc[2 * kv + 1][2], sacc[2 * kv + 1][3], ah[3], al[3]);
#pragma unroll
            for (int nf = 0; nf < 16; nf++) {
                uint32_t bb[4];
                LDMX4(bb, base + v_off + nf * 1152 + kv * 32);
                uint32_t bh[2] = {bb[0], bb[1]}, bl[2] = {bb[2], bb[3]};
                MMA4(O[nf], ah, bh);
                MMA4(O[nf], ah, bl);
                MMA4(O[nf], al, bh);
            }
        }
        __syncthreads();
    }

    // ---- merge key halves (reuse Q area: dead after last S) ----
    float* Osm = (float*)sm;               // [64][132]
    float* stats = (float*)(sm + 33792);   // [64][2] (m, l)
    const int lr0 = wq * 16 + qr, lr1 = lr0 + 8;
    __syncthreads();
    if (half == 1) {
#pragma unroll
        for (int nf = 0; nf < 16; nf++) {
            const int col = nf * 8 + qc * 2;
            *(float2*)&Osm[lr0 * 132 + col] = make_float2(O[nf][0], O[nf][1]);
            *(float2*)&Osm[lr1 * 132 + col] = make_float2(O[nf][2], O[nf][3]);
        }
        if (qc == 0) {
            stats[lr0 * 2] = m0; stats[lr0 * 2 + 1] = l0;
            stats[lr1 * 2] = m1; stats[lr1 * 2 + 1] = l1;
        }
    }
    __syncthreads();
    if (half == 0) {
        const float mB0 = stats[lr0 * 2], lB0 = stats[lr0 * 2 + 1];
        const float mB1 = stats[lr1 * 2], lB1 = stats[lr1 * 2 + 1];
        const float mF0 = fmaxf(m0, mB0), mF1 = fmaxf(m1, mB1);
        const float wA0 = __expf(m0 - mF0), wB0 = __expf(mB0 - mF0);
        const float wA1 = __expf(m1 - mF1), wB1 = __expf(mB1 - mF1);
        l0 = l0 * wA0 + lB0 * wB0;
        l1 = l1 * wA1 + lB1 * wB1;
        m0 = mF0; m1 = mF1;
#pragma unroll
        for (int nf = 0; nf < 16; nf++) {
            const int col = nf * 8 + qc * 2;
            float2 vb0 = *(float2*)&Osm[lr0 * 132 + col];
            float2 vb1 = *(float2*)&Osm[lr1 * 132 + col];
            O[nf][0] = O[nf][0] * wA0 + vb0.x * wB0;
            O[nf][1] = O[nf][1] * wA0 + vb0.y * wB0;
            O[nf][2] = O[nf][2] * wA1 + vb1.x * wB1;
            O[nf][3] = O[nf][3] * wA1 + vb1.y * wB1;
        }

        if (partial) {
            const int slot = ((b * 16 + (qt - 16)) << 1) + part;
            if (qc == 0) {
                g_pm[slot][lr0] = m0; g_pl[slot][lr0] = l0;
                g_pm[slot][lr1] = m1; g_pl[slot][lr1] = l1;
            }
#pragma unroll
            for (int nf = 0; nf < 16; nf++) {
                const int col = nf * 8 + qc * 2;
                *(float2*)&g_pO[slot][lr0][col] = make_float2(O[nf][0], O[nf][1]);
                *(float2*)&g_pO[slot][lr1][col] = make_float2(O[nf][2], O[nf][3]);
            }
        } else {
            const float inv0 = 1.f / l0, inv1 = 1.f / l1;
            const size_t row0 = bbase + qb + lr0;
#pragma unroll
            for (int nf = 0; nf < 16; nf++) {
                const int col = nf * 8 + qc * 2;
                uint32_t h, l;
                split2(O[nf][0] * inv0, O[nf][1] * inv0, h, l);
                ((uint32_t*)(g_ctxhi + row0 * DH))[col >> 1] = h;
                ((uint32_t*)(g_ctxlo + row0 * DH))[col >> 1] = l;
                split2(O[nf][2] * inv1, O[nf][3] * inv1, h, l);
                ((uint32_t*)(g_ctxhi + (row0 + 8) * DH))[col >> 1] = h;
                ((uint32_t*)(g_ctxlo + (row0 + 8) * DH))[col >> 1] = l;
            }
        }
    }
}

// combine partials for qt>=16: grid (16, 4), 256 threads (R12 verbatim).
__global__ void attn_combine() {
    const int qt = 16 + blockIdx.x, b = blockIdx.y;
    const int slotA = ((b * 16 + blockIdx.x) << 1), slotB = slotA + 1;
    const int tid = threadIdx.x;
    const int r = tid >> 2, seg = (tid & 3) * 32;
    const float mA = g_pm[slotA][r], mB = g_pm[slotB][r];
    const float m = fmaxf(mA, mB);
    float wA = __expf(mA - m), wB = __expf(mB - m);
    const float inv = 1.f / (g_pl[slotA][r] * wA + g_pl[slotB][r] * wB);
    wA *= inv; wB *= inv;
    const size_t grow = (size_t)b * SEQ + (size_t)qt * 64 + r;
#pragma unroll
    for (int c = 0; c < 32; c += 2) {
        const int col = seg + c;
        float2 a = *(float2*)&g_pO[slotA][r][col];
        float2 bv = *(float2*)&g_pO[slotB][r][col];
        uint32_t h, l;
        split2(a.x * wA + bv.x * wB, a.y * wA + bv.y * wB, h, l);
        ((uint32_t*)(g_ctxhi + grow * DH))[col >> 1] = h;
        ((uint32_t*)(g_ctxlo + grow * DH))[col >> 1] = l;
    }
}

// ---------------------------------------------------------------------------
extern "C" void kernel_launch(void* const* d_in, const int* in_sizes, int n_in,
                              void* d_out, int out_size)
{
    (void)in_sizes; (void)n_in; (void)out_size;
    const float* x  = (const float*)d_in[0];
    const float* wq = (const float*)d_in[1];
    const float* wk = (const float*)d_in[2];
    const float* wv = (const float*)d_in[3];
    const float* wo = (const float*)d_in[4];
    float* out = (float*)d_out;

    cudaFuncSetAttribute(qkv_mma_kernel,
                         cudaFuncAttributeMaxDynamicSharedMemorySize, QKV_SMEM);
    cudaFuncSetAttribute(out_mma_kernel,
                         cudaFuncAttributeMaxDynamicSharedMemorySize, OUT_SMEM);
    cudaFuncSetAttribute(attn_mma_kernel,
                         cudaFuncAttributeMaxDynamicSharedMemorySize, ATTN_SMEM);

    prep_w_qkv<<<dim3(DM, 3), DH>>>(wq, wk, wv);
    prep_wo<<<DH, 256>>>(wo);
    qkv_mma_kernel<<<dim3(ROWS / 64, 3), 256, QKV_SMEM>>>(x);
    prep_vt<<<dim3(SEQ / 64, BATCH), 256>>>();
    attn_mma_kernel<<<192, 256, ATTN_SMEM>>>();
    attn_combine<<<dim3(16, BATCH), 256>>>();
    out_mma_kernel<<<dim3(ROWS / 64, DM / 128), 256, OUT_SMEM>>>(out);
}

// round 17
// speedup vs baseline: 1.1525x; 1.0253x over previous
#include <cuda_runtime.h>
#include <cuda_bf16.h>
#include <cstdint>

#define BATCH 4
#define SEQ 2048
#define DM 1024
#define DH 128
#define ROWS (BATCH * SEQ)   // 8192

// ---------------------------------------------------------------------------
// Scratch (__device__ globals per allocation rules)
// ---------------------------------------------------------------------------
__device__ __align__(16) __nv_bfloat16 g_qhi[ROWS * DH];
__device__ __align__(16) __nv_bfloat16 g_qlo[ROWS * DH];
__device__ __align__(16) __nv_bfloat16 g_khi[ROWS * DH];
__device__ __align__(16) __nv_bfloat16 g_klo[ROWS * DH];
__device__ __align__(16) __nv_bfloat16 g_vthi[BATCH * DH * SEQ];  // [b][d][key]
__device__ __align__(16) __nv_bfloat16 g_vtlo[BATCH * DH * SEQ];
__device__ __align__(16) __nv_bfloat16 g_ctxhi[ROWS * DH];
__device__ __align__(16) __nv_bfloat16 g_ctxlo[ROWS * DH];
// split-K attention partials: slot = (b*16 + qt-16)*2 + part
__device__ __align__(16) float g_pO[128][64][DH];
__device__ float g_pm[128][64];
__device__ float g_pl[128][64];
// transposed bf16 hi/lo weights: wT[z][n][k] = w_z[k][n]
__device__ __align__(16) __nv_bfloat16 g_wThi[3 * DH * DM];
__device__ __align__(16) __nv_bfloat16 g_wTlo[3 * DH * DM];
__device__ __align__(16) __nv_bfloat16 g_woThi[DM * DH];
__device__ __align__(16) __nv_bfloat16 g_woTlo[DM * DH];

// ---------------------------------------------------------------------------
// helpers
// ---------------------------------------------------------------------------
__device__ __forceinline__ uint32_t smem_u32(const void* p) {
    uint32_t a;
    asm("{ .reg .u64 t; cvta.to.shared.u64 t, %1; cvt.u32.u64 %0, t; }"
        : "=r"(a) : "l"(p));
    return a;
}
__device__ __forceinline__ uint32_t pack_bf16x2(float x, float y) {
    __nv_bfloat162 t(__float2bfloat16(x), __float2bfloat16(y));  // x -> low
    return *(uint32_t*)&t;
}
__device__ __forceinline__ void split_bf16(float v, __nv_bfloat16& h, float& lo) {
    h = __float2bfloat16(v);
    lo = v - __bfloat162float(h);
}
__device__ __forceinline__ void split2(float x, float y, uint32_t& hi, uint32_t& lo) {
    __nv_bfloat16 hx, hy; float lx, ly;
    split_bf16(x, hx, lx); split_bf16(y, hy, ly);
    __nv_bfloat162 H(hx, hy);
    hi = *(uint32_t*)&H;
    lo = pack_bf16x2(lx, ly);
}

// mma.sync m16n8k16 bf16 -> f32 (HMMA pipe, target-portable)
#define MMA4(c, a, b) asm volatile( \
    "mma.sync.aligned.m16n8k16.row.col.f32.bf16.bf16.f32 " \
    "{%0,%1,%2,%3}, {%4,%5,%6,%7}, {%8,%9}, {%0,%1,%2,%3};" \
    : "+f"((c)[0]), "+f"((c)[1]), "+f"((c)[2]), "+f"((c)[3]) \
    : "r"((a)[0]), "r"((a)[1]), "r"((a)[2]), "r"((a)[3]), \
      "r"((b)[0]), "r"((b)[1]))

#define LDMX4(d, a) asm volatile( \
    "ldmatrix.sync.aligned.m8n8.x4.shared.b16 {%0,%1,%2,%3}, [%4];" \
    : "=r"((d)[0]), "=r"((d)[1]), "=r"((d)[2]), "=r"((d)[3]) : "r"(a))

#define CP_ASYNC16(dst, src) \
    asm volatile("cp.async.cg.shared.global [%0], [%1], 16;" \
                 :: "r"(dst), "l"(src) : "memory")
#define CP_COMMIT asm volatile("cp.async.commit_group;" ::: "memory")
#define CP_WAIT(n) asm volatile("cp.async.wait_group %0;" :: "n"(n) : "memory")

// ---------------------------------------------------------------------------
// Weight prep: one launch. z=0..2 -> wq/wk/wv transposed; z=3 -> wo (bx<DH).
// ---------------------------------------------------------------------------
__global__ void prep_w(const float* __restrict__ wq,
                       const float* __restrict__ wk,
                       const float* __restrict__ wv,
                       const float* __restrict__ wo) {
    const int z = blockIdx.y, k = blockIdx.x, n = threadIdx.x;   // 128 thr
    if (z < 3) {
        const float* w = (z == 0) ? wq : (z == 1) ? wk : wv;
        float v = w[k * DH + n];
        __nv_bfloat16 h; float lo; split_bf16(v, h, lo);
        size_t o = (size_t)z * DH * DM + (size_t)n * DM + k;
        g_wThi[o] = h; g_wTlo[o] = __float2bfloat16(lo);
    } else {
        if (k >= DH) return;
#pragma unroll
        for (int i = 0; i < 8; i++) {
            int nn = n + i * 128;
            float v = wo[(size_t)k * DM + nn];
            __nv_bfloat16 h; float lo; split_bf16(v, h, lo);
            g_woThi[(size_t)nn * DH + k] = h;
            g_woTlo[(size_t)nn * DH + k] = __float2bfloat16(lo);
        }
    }
}

// ---------------------------------------------------------------------------
// Generic warp-mma GEMM core, 3-stage cp.async pipeline (R12 structure).
// EPI: 0 = f32 C stores, 1 = split hi/lo bf16 stores, 2 = V transpose+split
//      into g_vt{hi,lo} (BM=64 tile = 64 keys x full DH).
// ---------------------------------------------------------------------------
#define ABY  5120
#define BBY  10240
#define STGB (2 * ABY + 2 * BBY)              // 30720
#define QKV_SMEM (3 * STGB + 2 * 8192)        // 108544
#define OUT_SMEM (3 * STGB)                   // 92160

template <bool SPLIT_A, int EPI>
__device__ __forceinline__ void gemm_core(
    const float* __restrict__ Af,
    const __nv_bfloat16* __restrict__ Ahi,
    const __nv_bfloat16* __restrict__ Alo, int lda,
    const __nv_bfloat16* __restrict__ Bhig,
    const __nv_bfloat16* __restrict__ Blog, int ldb,
    float* __restrict__ C,
    __nv_bfloat16* __restrict__ Chi, __nv_bfloat16* __restrict__ Clo,
    int ldc, int nc, size_t vbase)
{
    extern __shared__ char smg[];
    const uint32_t sbase = smem_u32(smg);
    const int tid  = threadIdx.x;
    const int lane = tid & 31;
    const int wid  = tid >> 5;
    const int warpM = wid >> 2;
    const int warpN = wid & 3;
    const int qr = lane >> 2, qc = lane & 3;

    float acc[2][4][4];
#pragma unroll
    for (int mt = 0; mt < 2; mt++)
#pragma unroll
        for (int nt = 0; nt < 4; nt++)
#pragma unroll
            for (int i = 0; i < 4; i++) acc[mt][nt][i] = 0.f;

    auto issue = [&](int c) {
        const uint32_t bstg = sbase + (c % 3) * STGB + 2 * ABY;
#pragma unroll
        for (int i = 0; i < 4; i++) {
            int u = tid + i * 256;
            int r = u >> 3, cc = u & 3, hf = (u >> 2) & 1;
            CP_ASYNC16(bstg + (hf ? BBY : 0) + r * 80 + cc * 16,
                       (const char*)((hf ? Blog : Bhig) +
                                     (size_t)r * ldb + c * 32 + cc * 8));
        }
        if (SPLIT_A) {
            const uint32_t fstg = sbase + 3 * STGB + (c & 1) * 8192;
#pragma unroll
            for (int i = 0; i < 2; i++) {
                int u = tid + i * 256;
                int r = u >> 3, j = u & 7;
                CP_ASYNC16(fstg + r * 128 + j * 16,
                           (const char*)(Af + (size_t)r * lda + c * 32 + j * 4));
            }
        } else {
            const uint32_t astg = sbase + (c % 3) * STGB;
#pragma unroll
            for (int i = 0; i < 2; i++) {
                int u = tid + i * 256;
                int r = u >> 3, cc = u & 3, hf = (u >> 2) & 1;
                CP_ASYNC16(astg + (hf ? ABY : 0) + r * 80 + cc * 16,
                           (const char*)((hf ? Alo : Ahi) +
                                         (size_t)r * lda + c * 32 + cc * 8));
            }
        }
    };

    issue(0); CP_COMMIT;
    if (nc > 1) { issue(1); CP_COMMIT; }

    const uint32_t aoff_hi = (warpM * 32 + (lane & 15)) * 80 + ((lane >> 4) & 1) * 16;
    const uint32_t aoff_lo = aoff_hi + ABY;
    const uint32_t boff = 2 * ABY + ((lane & 16) ? BBY : 0) +
                          (warpN * 32 + (lane & 7)) * 80 + ((lane >> 3) & 1) * 16;

    for (int c = 0; c < nc; c++) {
        if (c + 1 < nc) CP_WAIT(1); else CP_WAIT(0);
        __syncthreads();

        const uint32_t bufb = sbase + (c % 3) * STGB;
        if (SPLIT_A) {
            const uint32_t fstg = sbase + 3 * STGB + (c & 1) * 8192;
#pragma unroll
            for (int i = 0; i < 2; i++) {
                int u = tid + i * 256;
                int r = u >> 3, j = u & 7;
                float vx, vy, vz, vw;
                asm volatile("ld.shared.v4.f32 {%0,%1,%2,%3}, [%4];"
                             : "=f"(vx), "=f"(vy), "=f"(vz), "=f"(vw)
                             : "r"(fstg + r * 128 + j * 16));
                uint32_t h0, l0, h1, l1;
                split2(vx, vy, h0, l0);
                split2(vz, vw, h1, l1);
                asm volatile("st.shared.v2.b32 [%0], {%1,%2};"
                             :: "r"(bufb + r * 80 + j * 8), "r"(h0), "r"(h1) : "memory");
                asm volatile("st.shared.v2.b32 [%0], {%1,%2};"
                             :: "r"(bufb + ABY + r * 80 + j * 8), "r"(l0), "r"(l1) : "memory");
            }
            __syncthreads();
        }
        if (c + 2 < nc) { issue(c + 2); CP_COMMIT; }

#pragma unroll
        for (int s = 0; s < 2; s++) {
            uint32_t ah[2][4], al[2][4];
#pragma unroll
            for (int mt = 0; mt < 2; mt++) {
                LDMX4(ah[mt], bufb + aoff_hi + mt * 16 * 80 + s * 32);
                LDMX4(al[mt], bufb + aoff_lo + mt * 16 * 80 + s * 32);
            }
#pragma unroll
            for (int nt = 0; nt < 4; nt++) {
                uint32_t bb[4];
                LDMX4(bb, bufb + boff + nt * 8 * 80 + s * 32);
                uint32_t bh[2] = {bb[0], bb[1]}, bl[2] = {bb[2], bb[3]};
#pragma unroll
                for (int mt = 0; mt < 2; mt++) {
                    MMA4(acc[mt][nt], ah[mt], bh);
                    MMA4(acc[mt][nt], ah[mt], bl);
                    MMA4(acc[mt][nt], al[mt], bh);
                }
            }
        }
    }

    if (EPI == 2) {
        // V epilogue: stage f32 tile [key(row 0..63)][d(col 0..127)] in smem,
        // then transpose + hi/lo split into g_vt{hi,lo}[b][d][key].
        float* ts = (float*)smg;      // 64 x 132 f32 = 33792 B (reuses stages)
        __syncthreads();              // all warps done reading stage buffers
#pragma unroll
        for (int mt = 0; mt < 2; mt++)
#pragma unroll
            for (int nt = 0; nt < 4; nt++) {
                int r = warpM * 32 + mt * 16 + qr;
                int col = warpN * 32 + nt * 8 + qc * 2;
                *(float2*)&ts[r * 132 + col] =
                    make_float2(acc[mt][nt][0], acc[mt][nt][1]);
                *(float2*)&ts[(r + 8) * 132 + col] =
                    make_float2(acc[mt][nt][2], acc[mt][nt][3]);
            }
        __syncthreads();
        const int d = tid >> 1, hf2 = tid & 1;
        uint32_t* ohi = (uint32_t*)(g_vthi + vbase + (size_t)d * SEQ) + hf2 * 16;
        uint32_t* olo = (uint32_t*)(g_vtlo + vbase + (size_t)d * SEQ) + hf2 * 16;
#pragma unroll
        for (int j = 0; j < 16; j++) {
            int key = hf2 * 32 + j * 2;
            uint32_t hv, lv;
            split2(ts[key * 132 + d], ts[(key + 1) * 132 + d], hv, lv);
            ohi[j] = hv; olo[j] = lv;
        }
        return;
    }

#pragma unroll
    for (int mt = 0; mt < 2; mt++)
#pragma unroll
        for (int nt = 0; nt < 4; nt++) {
            int r = warpM * 32 + mt * 16 + qr;
            int col = warpN * 32 + nt * 8 + qc * 2;
            if (EPI == 1) {
                uint32_t h0, l0, h1, l1;
                split2(acc[mt][nt][0], acc[mt][nt][1], h0, l0);
                split2(acc[mt][nt][2], acc[mt][nt][3], h1, l1);
                ((uint32_t*)(Chi + (size_t)r * ldc))[col >> 1] = h0;
                ((uint32_t*)(Clo + (size_t)r * ldc))[col >> 1] = l0;
                ((uint32_t*)(Chi + (size_t)(r + 8) * ldc))[col >> 1] = h1;
                ((uint32_t*)(Clo + (size_t)(r + 8) * ldc))[col >> 1] = l1;
            } else {
                *(float2*)(C + (size_t)r * ldc + col) =
                    make_float2(acc[mt][nt][0], acc[mt][nt][1]);
                *(float2*)(C + (size_t)(r + 8) * ldc + col) =
                    make_float2(acc[mt][nt][2], acc[mt][nt][3]);
            }
        }
}

// qkv: grid (128, 3): 64 rows/CTA, K=1024 (nc=32), N=128. A = raw f32 x.
// z=0 -> Q hi/lo, z=1 -> K hi/lo, z=2 -> V transposed+split (fused).
__global__ __launch_bounds__(256, 2) void qkv_mma_kernel(const float* __restrict__ x) {
    const int z = blockIdx.y, bx = blockIdx.x;
    const __nv_bfloat16* Bh = g_wThi + (size_t)z * DH * DM;
    const __nv_bfloat16* Bl = g_wTlo + (size_t)z * DH * DM;
    const size_t rb = (size_t)bx * 64;
    if (z == 0) {
        gemm_core<true, 1>(x + rb * DM, nullptr, nullptr, DM, Bh, Bl, DM,
                           nullptr, g_qhi + rb * DH, g_qlo + rb * DH, DH, 32, 0);
    } else if (z == 1) {
        gemm_core<true, 1>(x + rb * DM, nullptr, nullptr, DM, Bh, Bl, DM,
                           nullptr, g_khi + rb * DH, g_klo + rb * DH, DH, 32, 0);
    } else {
        const int b  = (int)(rb >> 11);           // rb / SEQ
        const int kb = (int)(rb & (SEQ - 1));
        const size_t vbase = (size_t)b * DH * SEQ + kb;
        gemm_core<true, 2>(x + rb * DM, nullptr, nullptr, DM, Bh, Bl, DM,
                           nullptr, nullptr, nullptr, DH, 32, vbase);
    }
}

// out: grid (128, 8): 64 rows, n-slab 128, K=128 (nc=4). A = ctx hi/lo.
__global__ __launch_bounds__(256, 2) void out_mma_kernel(float* __restrict__ out) {
    const int bx = blockIdx.x, by = blockIdx.y;
    const __nv_bfloat16* Bh = g_woThi + (size_t)by * 128 * DH;
    const __nv_bfloat16* Bl = g_woTlo + (size_t)by * 128 * DH;
    float* C = out + (size_t)bx * 64 * DM + by * 128;
    gemm_core<false, 0>(nullptr, g_ctxhi + (size_t)bx * 64 * DH,
                        g_ctxlo + (size_t)bx * 64 * DH, DH,
                        Bh, Bl, DH, C, nullptr, nullptr, DM, 4, 0);
}

// ---------------------------------------------------------------------------
// Tensor-core causal flash attention, split-K, DOUBLE-buffered (R12 verbatim).
// grid = 192; 128 thr; smem = 178176 B.
// ---------------------------------------------------------------------------
#define ATTN_SMEM 178176

__device__ __forceinline__ void attn_issue_tile(
    uint32_t sbase, int tid, int b, int kt, int p, size_t bbase)
{
    const uint32_t base = sbase + 34816 + p * 71680;
    const int k0 = kt * 64;
    const char* khi_g = (const char*)(g_khi + (bbase + k0) * DH);
    const char* klo_g = (const char*)(g_klo + (bbase + k0) * DH);
    const char* vhi_g = (const char*)g_vthi + (((size_t)b * DH) * SEQ + k0) * 2;
    const char* vlo_g = (const char*)g_vtlo + (((size_t)b * DH) * SEQ + k0) * 2;
#pragma unroll
    for (int i = 0; i < 8; i++) {
        int id = tid + i * 128;
        int r  = id >> 4, off  = (id & 15) * 16;   // K: 64 rows x 256B
        CP_ASYNC16(base + r * 272 + off, khi_g + (size_t)r * 256 + off);
        CP_ASYNC16(base + 17408 + r * 272 + off, klo_g + (size_t)r * 256 + off);
        int rv = id >> 3, offv = (id & 7) * 16;    // Vt: 128 rows x 128B
        CP_ASYNC16(base + 34816 + rv * 144 + offv,
                   vhi_g + (size_t)rv * (SEQ * 2) + offv);
        CP_ASYNC16(base + 53248 + rv * 144 + offv,
                   vlo_g + (size_t)rv * (SEQ * 2) + offv);
    }
}

__global__ __launch_bounds__(128, 1) void attn_mma_kernel()
{
    extern __shared__ char sm[];
    const uint32_t sbase = smem_u32(sm);
    const int tid  = threadIdx.x;
    const int lane = tid & 31;
    const int wq   = tid >> 5;
    const int qr   = lane >> 2, qc = lane & 3;

    const int bid = blockIdx.x;
    int b, qt, kt0, kt1, part;
    bool partial;
    if (bid < 64) {
        b = bid & 3; qt = 16 + (bid >> 2); kt0 = 0; kt1 = 15;
        partial = true; part = 0;
    } else if (bid < 128) {
        int i = bid - 64;
        b = i & 3; qt = 31 - (i >> 2); kt0 = 16; kt1 = qt;
        partial = true; part = 1;
    } else {
        int i = bid - 128;
        b = i & 3; qt = 15 - (i >> 2); kt0 = 0; kt1 = qt;
        partial = false; part = 0;
    }
    const int qb = qt * 64;
    const size_t bbase = (size_t)b * SEQ;
    const int ntiles = kt1 - kt0 + 1;
    const float scale = 0.08838834764831845f;

    {
        const char* qhi_g = (const char*)(g_qhi + (bbase + qb) * DH);
        const char* qlo_g = (const char*)(g_qlo + (bbase + qb) * DH);
#pragma unroll
        for (int i = 0; i < 8; i++) {
            int id = tid + i * 128;
            int r = id >> 4, off = (id & 15) * 16;
            CP_ASYNC16(sbase + r * 272 + off, qhi_g + (size_t)r * 256 + off);
            CP_ASYNC16(sbase + 17408 + r * 272 + off, qlo_g + (size_t)r * 256 + off);
        }
        attn_issue_tile(sbase, tid, b, kt0, 0, bbase);
        CP_COMMIT;
    }

    const uint32_t q_hi_addr = sbase + (wq * 16 + (lane & 15)) * 272 +
                               ((lane >> 4) & 1) * 16;
    const uint32_t q_lo_addr = q_hi_addr + 17408;
    const uint32_t k_off = ((lane & 16) ? 17408u : 0u) +
                           (lane & 7) * 272 + ((lane >> 3) & 1) * 16;
    const uint32_t v_off = 34816u + ((lane & 16) ? 18432u : 0u) +
                           (lane & 7) * 144 + ((lane >> 3) & 1) * 16;

    float O[16][4];
#pragma unroll
    for (int nf = 0; nf < 16; nf++)
#pragma unroll
        for (int i = 0; i < 4; i++) O[nf][i] = 0.f;
    float m0 = -1e30f, m1 = -1e30f, l0 = 0.f, l1 = 0.f;

    for (int t = 0; t < ntiles; t++) {
        const int kt = kt0 + t;
        const int p = t & 1;
        if (t + 1 < ntiles) {
            attn_issue_tile(sbase, tid, b, kt + 1, p ^ 1, bbase);
            CP_COMMIT;
            CP_WAIT(1);
        } else {
            CP_WAIT(0);
        }
        __syncthreads();

        const uint32_t base = sbase + 34816 + p * 71680;

        float sacc[8][4];
#pragma unroll
        for (int nf = 0; nf < 8; nf++)
#pragma unroll
            for (int i = 0; i < 4; i++) sacc[nf][i] = 0.f;

#pragma unroll
        for (int kf = 0; kf < 8; kf++) {
            uint32_t ah[4], al[4];
            LDMX4(ah, q_hi_addr + kf * 32);
            LDMX4(al, q_lo_addr + kf * 32);
#pragma unroll
            for (int nf = 0; nf < 8; nf++) {
                uint32_t bb[4];
                LDMX4(bb, base + k_off + nf * 2176 + kf * 32);
                uint32_t bh[2] = {bb[0], bb[1]}, bl[2] = {bb[2], bb[3]};
                MMA4(sacc[nf], ah, bh);
                MMA4(sacc[nf], ah, bl);
                MMA4(sacc[nf], al, bh);
            }
        }

#pragma unroll
        for (int nf = 0; nf < 8; nf++)
#pragma unroll
            for (int i = 0; i < 4; i++) sacc[nf][i] *= scale;
        if (kt == qt) {
            const int q0 = wq * 16 + qr, q1 = q0 + 8;
#pragma unroll
            for (int nf = 0; nf < 8; nf++) {
                const int key = nf * 8 + qc * 2;
                if (key > q0)     sacc[nf][0] = -1e30f;
                if (key + 1 > q0) sacc[nf][1] = -1e30f;
                if (key > q1)     sacc[nf][2] = -1e30f;
                if (key + 1 > q1) sacc[nf][3] = -1e30f;
            }
        }

        float mt0 = -1e30f, mt1 = -1e30f;
#pragma unroll
        for (int nf = 0; nf < 8; nf++) {
            mt0 = fmaxf(mt0, fmaxf(sacc[nf][0], sacc[nf][1]));
            mt1 = fmaxf(mt1, fmaxf(sacc[nf][2], sacc[nf][3]));
        }
        mt0 = fmaxf(mt0, __shfl_xor_sync(0xffffffffu, mt0, 1));
        mt0 = fmaxf(mt0, __shfl_xor_sync(0xffffffffu, mt0, 2));
        mt1 = fmaxf(mt1, __shfl_xor_sync(0xffffffffu, mt1, 1));
        mt1 = fmaxf(mt1, __shfl_xor_sync(0xffffffffu, mt1, 2));
        const float nm0 = fmaxf(m0, mt0), nm1 = fmaxf(m1, mt1);
        const float corr0 = __expf(m0 - nm0), corr1 = __expf(m1 - nm1);
        m0 = nm0; m1 = nm1;

        float rs0 = 0.f, rs1 = 0.f;
#pragma unroll
        for (int nf = 0; nf < 8; nf++) {
            sacc[nf][0] = __expf(sacc[nf][0] - nm0);
            sacc[nf][1] = __expf(sacc[nf][1] - nm0);
            sacc[nf][2] = __expf(sacc[nf][2] - nm1);
            sacc[nf][3] = __expf(sacc[nf][3] - nm1);
            rs0 += sacc[nf][0] + sacc[nf][1];
            rs1 += sacc[nf][2] + sacc[nf][3];
        }
        rs0 += __shfl_xor_sync(0xffffffffu, rs0, 1);
        rs0 += __shfl_xor_sync(0xffffffffu, rs0, 2);
        rs1 += __shfl_xor_sync(0xffffffffu, rs1, 1);
        rs1 += __shfl_xor_sync(0xffffffffu, rs1, 2);
        l0 = l0 * corr0 + rs0;
        l1 = l1 * corr1 + rs1;
#pragma unroll
        for (int nf = 0; nf < 16; nf++) {
            O[nf][0] *= corr0; O[nf][1] *= corr0;
            O[nf][2] *= corr1; O[nf][3] *= corr1;
        }

#pragma unroll
        for (int kv = 0; kv < 4; kv++) {
            uint32_t ah[4], al[4];
            split2(sacc[2 * kv][0],     sacc[2 * kv][1],     ah[0], al[0]);
            split2(sacc[2 * kv][2],     sacc[2 * kv][3],     ah[1], al[1]);
            split2(sacc[2 * kv + 1][0], sacc[2 * kv + 1][1], ah[2], al[2]);
            split2(sacc[2 * kv + 1][2], sacc[2 * kv + 1][3], ah[3], al[3]);
#pragma unroll
            for (int nf = 0; nf < 16; nf++) {
                uint32_t bb[4];
                LDMX4(bb, base + v_off + nf * 1152 + kv * 32);
                uint32_t bh[2] = {bb[0], bb[1]}, bl[2] = {bb[2], bb[3]};
                MMA4(O[nf], ah, bh);
                MMA4(O[nf], ah, bl);
                MMA4(O[nf], al, bh);
            }
        }
        __syncthreads();
    }

    if (partial) {
        const int slot = ((b * 16 + (qt - 16)) << 1) + part;
        const int lr0 = wq * 16 + qr, lr1 = lr0 + 8;
        if (qc == 0) {
            g_pm[slot][lr0] = m0; g_pl[slot][lr0] = l0;
            g_pm[slot][lr1] = m1; g_pl[slot][lr1] = l1;
        }
#pragma unroll
        for (int nf = 0; nf < 16; nf++) {
            const int col = nf * 8 + qc * 2;
            *(float2*)&g_pO[slot][lr0][col] = make_float2(O[nf][0], O[nf][1]);
            *(float2*)&g_pO[slot][lr1][col] = make_float2(O[nf][2], O[nf][3]);
        }
    } else {
        const float inv0 = 1.f / l0, inv1 = 1.f / l1;
        const size_t row0 = bbase + qb + wq * 16 + qr;
#pragma unroll
        for (int nf = 0; nf < 16; nf++) {
            const int col = nf * 8 + qc * 2;
            uint32_t h, l;
            split2(O[nf][0] * inv0, O[nf][1] * inv0, h, l);
            ((uint32_t*)(g_ctxhi + row0 * DH))[col >> 1] = h;
            ((uint32_t*)(g_ctxlo + row0 * DH))[col >> 1] = l;
            split2(O[nf][2] * inv1, O[nf][3] * inv1, h, l);
            ((uint32_t*)(g_ctxhi + (row0 + 8) * DH))[col >> 1] = h;
            ((uint32_t*)(g_ctxlo + (row0 + 8) * DH))[col >> 1] = l;
        }
    }
}

// combine partials for qt>=16: grid (16, 4), 256 threads.
__global__ void attn_combine() {
    const int qt = 16 + blockIdx.x, b = blockIdx.y;
    const int slotA = ((b * 16 + blockIdx.x) << 1), slotB = slotA + 1;
    const int tid = threadIdx.x;
    const int r = tid >> 2, seg = (tid & 3) * 32;
    const float mA = g_pm[slotA][r], mB = g_pm[slotB][r];
    const float m = fmaxf(mA, mB);
    float wA = __expf(mA - m), wB = __expf(mB - m);
    const float inv = 1.f / (g_pl[slotA][r] * wA + g_pl[slotB][r] * wB);
    wA *= inv; wB *= inv;
    const size_t grow = (size_t)b * SEQ + (size_t)qt * 64 + r;
#pragma unroll
    for (int c = 0; c < 32; c += 2) {
        const int col = seg + c;
        float2 a = *(float2*)&g_pO[slotA][r][col];
        float2 bv = *(float2*)&g_pO[slotB][r][col];
        uint32_t h, l;
        split2(a.x * wA + bv.x * wB, a.y * wA + bv.y * wB, h, l);
        ((uint32_t*)(g_ctxhi + grow * DH))[col >> 1] = h;
        ((uint32_t*)(g_ctxlo + grow * DH))[col >> 1] = l;
    }
}

// ---------------------------------------------------------------------------
extern "C" void kernel_launch(void* const* d_in, const int* in_sizes, int n_in,
                              void* d_out, int out_size)
{
    (void)in_sizes; (void)n_in; (void)out_size;
    const float* x  = (const float*)d_in[0];
    const float* wq = (const float*)d_in[1];
    const float* wk = (const float*)d_in[2];
    const float* wv = (const float*)d_in[3];
    const float* wo = (const float*)d_in[4];
    float* out = (float*)d_out;

    cudaFuncSetAttribute(qkv_mma_kernel,
                         cudaFuncAttributeMaxDynamicSharedMemorySize, QKV_SMEM);
    cudaFuncSetAttribute(out_mma_kernel,
                         cudaFuncAttributeMaxDynamicSharedMemorySize, OUT_SMEM);
    cudaFuncSetAttribute(attn_mma_kernel,
                         cudaFuncAttributeMaxDynamicSharedMemorySize, ATTN_SMEM);

    prep_w<<<dim3(DM, 4), DH>>>(wq, wk, wv, wo);
    qkv_mma_kernel<<<dim3(ROWS / 64, 3), 256, QKV_SMEM>>>(x);
    attn_mma_kernel<<<192, 128, ATTN_SMEM>>>();
    attn_combine<<<dim3(16, BATCH), 256>>>();
    out_mma_kernel<<<dim3(ROWS / 64, DM / 128), 256, OUT_SMEM>>>(out);
}